// round 2
// baseline (speedup 1.0000x reference)
#include <cuda_runtime.h>

typedef unsigned long long ull;

#define TT 512
#define BB 512
#define HH 128
#define G4 512

// ---------------- device-global scratch (no allocations allowed) ------------
__device__ float g_xg[134217728];        // [T*B][4H] gate preactivations
__device__ float g_h0[33554432];         // [T*B][H]
__device__ float g_h1[33554432];         // [T*B][H]
__device__ ull   g_ws3[3][64 * 384];     // W_hh gates i,f,g: [k2][j] k-pairs
__device__ ull   g_wo [3][64 * 128];     // W_hh gate o:      [k2][jo] k-pairs
__device__ ull   g_wip[2][64 * 512];     // W_ih layers 1,2:  [k2][j] k-pairs
__device__ float g_bias[3][512];         // b_ih + b_hh

// ---------------- helpers ---------------------------------------------------
__device__ __forceinline__ void fma2(ull& d, ull a, ull b) {
    asm("fma.rn.f32x2 %0, %1, %2, %0;" : "+l"(d) : "l"(a), "l"(b));
}
__device__ __forceinline__ ull pack2(float a, float b) {
    ull r; asm("mov.b64 %0, {%1,%2};" : "=l"(r) : "f"(a), "f"(b)); return r;
}
__device__ __forceinline__ float sum2(ull v) {
    float lo, hi; asm("mov.b64 {%0,%1}, %2;" : "=f"(lo), "=f"(hi) : "l"(v));
    return lo + hi;
}
__device__ __forceinline__ float sigf(float x) {
    return __fdividef(1.f, 1.f + __expf(-x));
}
__device__ __forceinline__ float tanh_(float x) {
    return 1.f - __fdividef(2.f, 1.f + __expf(2.f * x));
}

// ---------------- weight prep ------------------------------------------------
__global__ void prep_whh_kernel(const float* __restrict__ whh,
                                const float* __restrict__ bih,
                                const float* __restrict__ bhh, int l) {
    int idx = blockIdx.x * 256 + threadIdx.x;
    if (idx < 32768) {
        int k2 = idx >> 9, j = idx & 511;
        ull p = pack2(whh[j * HH + 2 * k2], whh[j * HH + 2 * k2 + 1]);
        if (j < 384) g_ws3[l][k2 * 384 + j];
        if (j < 384) g_ws3[l][k2 * 384 + j] = p;
        else         g_wo [l][k2 * 128 + (j - 384)] = p;
    } else if (idx < 33280) {
        int j = idx - 32768;
        g_bias[l][j] = bih[j] + bhh[j];
    }
}

__global__ void prep_wih_kernel(const float* __restrict__ wih, int p) {
    int idx = blockIdx.x * 256 + threadIdx.x;
    if (idx < 32768) {
        int k2 = idx >> 9, j = idx & 511;
        g_wip[p][k2 * 512 + j] = pack2(wih[j * HH + 2 * k2], wih[j * HH + 2 * k2 + 1]);
    }
}

// ---------------- layer-0 input projection (K = 8) ---------------------------
__global__ __launch_bounds__(256) void proj0_kernel(const float* __restrict__ x,
                                                    const float* __restrict__ w0) {
    __shared__ float ws[4096], xs[4096], bs[512];
    int t = blockIdx.x, tid = threadIdx.x;
    for (int i = tid; i < 4096; i += 256) ws[i] = w0[i];
    for (int i = tid; i < 512; i += 256) bs[i] = g_bias[0][i];
    for (int i = tid; i < 4096; i += 256) {
        int b = i >> 3, f = i & 7;
        xs[i] = x[(size_t)b * 4096 + t * 8 + f];   // x[b][t][f]
    }
    __syncthreads();
    int j0 = tid, j1 = tid + 256;
    float w0r[8], w1r[8];
#pragma unroll
    for (int f = 0; f < 8; f++) { w0r[f] = ws[j0 * 8 + f]; w1r[f] = ws[j1 * 8 + f]; }
    float bz0 = bs[j0], bz1 = bs[j1];
    float* outt = g_xg + (size_t)t * BB * G4;
    for (int b = 0; b < BB; b++) {
        float a0 = bz0, a1 = bz1;
#pragma unroll
        for (int f = 0; f < 8; f++) {
            float xv = xs[b * 8 + f];
            a0 = fmaf(xv, w0r[f], a0);
            a1 = fmaf(xv, w1r[f], a1);
        }
        outt[(size_t)b * G4 + j0] = a0;
        outt[(size_t)b * G4 + j1] = a1;
    }
}

// ---------------- layers 1,2 input projection: f32x2 tiled GEMM --------------
// xg[m][n] = sum_k hin[m][k]*w_ih[n][k] + bias[n];  tile 64m x 128n, K=128
__global__ __launch_bounds__(256, 2) void proj_mid_kernel(int p) {
    extern __shared__ ull ps[];
    ull* a_s = ps;             // [64 m][64 k2]
    ull* b_s = ps + 64 * 64;   // [64 k2][128 n]
    const float* hin = p ? g_h1 : g_h0;
    const ull* wip = g_wip[p];
    const float* bias = g_bias[p + 1];
    int tid = threadIdx.x;
    int mbase = blockIdx.x * 64;
    int nbase = blockIdx.y * 128;
#pragma unroll
    for (int it = 0; it < 8; it++) {
        int idx = tid + it * 256;
        int row = idx >> 5, k4 = idx & 31;
        float4 v = *(const float4*)(hin + (size_t)(mbase + row) * HH + k4 * 4);
        a_s[row * 64 + 2 * k4]     = pack2(v.x, v.y);
        a_s[row * 64 + 2 * k4 + 1] = pack2(v.z, v.w);
    }
#pragma unroll
    for (int it = 0; it < 32; it++) {
        int idx = tid + it * 256;
        b_s[idx] = wip[(idx >> 7) * G4 + nbase + (idx & 127)];
    }
    __syncthreads();
    int tm = (tid >> 5) * 8, tn = tid & 31;
    ull acc[8][4];
#pragma unroll
    for (int i = 0; i < 8; i++)
#pragma unroll
        for (int j = 0; j < 4; j++) acc[i][j] = 0ull;
#pragma unroll 2
    for (int q = 0; q < 32; q++) {
        ulonglong2 av[8];
#pragma unroll
        for (int i = 0; i < 8; i++)
            av[i] = *(const ulonglong2*)(a_s + (tm + i) * 64 + 2 * q);
        ull bv0[4], bv1[4];
#pragma unroll
        for (int j = 0; j < 4; j++) {
            bv0[j] = b_s[(2 * q) * 128 + tn + 32 * j];
            bv1[j] = b_s[(2 * q + 1) * 128 + tn + 32 * j];
        }
#pragma unroll
        for (int i = 0; i < 8; i++)
#pragma unroll
            for (int j = 0; j < 4; j++) {
                fma2(acc[i][j], av[i].x, bv0[j]);
                fma2(acc[i][j], av[i].y, bv1[j]);
            }
    }
    float bb[4];
#pragma unroll
    for (int j = 0; j < 4; j++) bb[j] = bias[nbase + tn + 32 * j];
#pragma unroll
    for (int i = 0; i < 8; i++) {
        float* rowp = g_xg + (size_t)(mbase + tm + i) * G4 + nbase;
#pragma unroll
        for (int j = 0; j < 4; j++) rowp[tn + 32 * j] = sum2(acc[i][j]) + bb[j];
    }
}

// ---------------- recurrent LSTM layer ---------------------------------------
// 128 CTAs x 256 thr; CTA owns 4 batch rows. Gates i,f,g in smem; o streamed.
#define REC_HV \
    ulonglong2 hv0 = *(const ulonglong2*)(hf + 0 * HH + 4 * q); \
    ulonglong2 hv1 = *(const ulonglong2*)(hf + 1 * HH + 4 * q); \
    ulonglong2 hv2 = *(const ulonglong2*)(hf + 2 * HH + 4 * q); \
    ulonglong2 hv3 = *(const ulonglong2*)(hf + 3 * HH + 4 * q);
#define REC_FMAS \
    fma2(acc0[0], hv0.x, wa0); fma2(acc0[0], hv0.y, wb0); \
    fma2(acc0[1], hv1.x, wa0); fma2(acc0[1], hv1.y, wb0); \
    fma2(acc0[2], hv2.x, wa0); fma2(acc0[2], hv2.y, wb0); \
    fma2(acc0[3], hv3.x, wa0); fma2(acc0[3], hv3.y, wb0); \
    fma2(acc1[0], hv0.x, wa1); fma2(acc1[0], hv0.y, wb1); \
    fma2(acc1[1], hv1.x, wa1); fma2(acc1[1], hv1.y, wb1); \
    fma2(acc1[2], hv2.x, wa1); fma2(acc1[2], hv2.y, wb1); \
    fma2(acc1[3], hv3.x, wa1); fma2(acc1[3], hv3.y, wb1);

__global__ __launch_bounds__(256, 1) void rec_kernel(int l, int outsel) {
    extern __shared__ char smraw[];
    ull*   ws = (ull*)smraw;                            // [64][384] 192KB
    float* hf = (float*)(smraw + 64 * 384 * 8);         // [4][128]  2KB
    float* gv = hf + 4 * HH;                            // [512][6]  12KB

    const ull* wsg = g_ws3[l];
    const ull* wog = g_wo[l];
    float* hout = outsel ? g_h1 : g_h0;

    int tid = threadIdx.x;
    int b0 = blockIdx.x * 4;

    for (int i = tid; i < 64 * 384; i += 256) ws[i] = wsg[i];
    hf[tid] = 0.f; hf[tid + 256] = 0.f;
    int hh = tid & 127, rp = tid >> 7;
    float c0 = 0.f, c1 = 0.f;
    int j0 = tid, j1 = tid + 256, jo = tid - 128;
    __syncthreads();

    for (int t = 0; t < TT; t++) {
        const float* xrow = g_xg + ((size_t)t * BB + b0) * G4;
        float xa0[4], xa1[4];
#pragma unroll
        for (int r = 0; r < 4; r++) {
            xa0[r] = xrow[r * G4 + j0];
            xa1[r] = xrow[r * G4 + j1];
        }
        ull acc0[4] = {0, 0, 0, 0}, acc1[4] = {0, 0, 0, 0};
        if (tid < 128) {      // j1 = g-gate (smem)
#pragma unroll 4
            for (int q = 0; q < 32; q++) {
                REC_HV
                ull wa0 = ws[(2 * q) * 384 + j0], wb0 = ws[(2 * q + 1) * 384 + j0];
                ull wa1 = ws[(2 * q) * 384 + j1], wb1 = ws[(2 * q + 1) * 384 + j1];
                REC_FMAS
            }
        } else {              // j1 = o-gate (global, L2-resident)
            const ull* wop = wog + jo;
#pragma unroll 8
            for (int q = 0; q < 32; q++) {
                REC_HV
                ull wa0 = ws[(2 * q) * 384 + j0], wb0 = ws[(2 * q + 1) * 384 + j0];
                ull wa1 = wop[(size_t)(2 * q) * 128], wb1 = wop[(size_t)(2 * q + 1) * 128];
                REC_FMAS
            }
        }
#pragma unroll
        for (int r = 0; r < 4; r++) {
            gv[j0 * 6 + r] = sum2(acc0[r]) + xa0[r];
            gv[j1 * 6 + r] = sum2(acc1[r]) + xa1[r];
        }
        __syncthreads();
        {
            int r0 = rp * 2, r1 = rp * 2 + 1;
            float iv0 = gv[hh * 6 + r0],            iv1 = gv[hh * 6 + r1];
            float fv0 = gv[(HH + hh) * 6 + r0],     fv1 = gv[(HH + hh) * 6 + r1];
            float gg0 = gv[(2 * HH + hh) * 6 + r0], gg1 = gv[(2 * HH + hh) * 6 + r1];
            float ov0 = gv[(3 * HH + hh) * 6 + r0], ov1 = gv[(3 * HH + hh) * 6 + r1];
            c0 = sigf(fv0) * c0 + sigf(iv0) * tanh_(gg0);
            c1 = sigf(fv1) * c1 + sigf(iv1) * tanh_(gg1);
            float hn0 = sigf(ov0) * tanh_(c0);
            float hn1 = sigf(ov1) * tanh_(c1);
            hf[r0 * HH + hh] = hn0;
            hf[r1 * HH + hh] = hn1;
            hout[((size_t)t * BB + b0 + r0) * HH + hh] = hn0;
            hout[((size_t)t * BB + b0 + r1) * HH + hh] = hn1;
        }
        __syncthreads();
    }
}

// ---------------- FC head ----------------------------------------------------
__global__ __launch_bounds__(128) void head_kernel(const float* __restrict__ fc1w,
                                                   const float* __restrict__ fc1b,
                                                   const float* __restrict__ fc2w,
                                                   const float* __restrict__ fc2b,
                                                   float* __restrict__ out) {
    __shared__ float last[128], z[128];
    int b = blockIdx.x, tid = threadIdx.x;
    last[tid] = g_h0[((size_t)(TT - 1) * BB + b) * HH + tid];
    __syncthreads();
    float a = fc1b[tid];
#pragma unroll 4
    for (int k = 0; k < HH; k++) a = fmaf(last[k], fc1w[tid * HH + k], a);
    z[tid] = fmaxf(a, 0.f);
    __syncthreads();
    if (tid < 7) {
        float y = fc2b[tid];
#pragma unroll 4
        for (int k = 0; k < HH; k++) y = fmaf(z[k], fc2w[tid * HH + k], y);
        out[b * 7 + tid] = y;
    }
}

// ---------------- launcher ---------------------------------------------------
extern "C" void kernel_launch(void* const* d_in, const int* in_sizes, int n_in,
                              void* d_out, int out_size) {
    (void)in_sizes; (void)n_in; (void)out_size;
    const float* x    = (const float*)d_in[0];
    const float* wih0 = (const float*)d_in[1];
    const float* whh0 = (const float*)d_in[2];
    const float* bih0 = (const float*)d_in[3];
    const float* bhh0 = (const float*)d_in[4];
    const float* wih1 = (const float*)d_in[5];
    const float* whh1 = (const float*)d_in[6];
    const float* bih1 = (const float*)d_in[7];
    const float* bhh1 = (const float*)d_in[8];
    const float* wih2 = (const float*)d_in[9];
    const float* whh2 = (const float*)d_in[10];
    const float* bih2 = (const float*)d_in[11];
    const float* bhh2 = (const float*)d_in[12];
    const float* fc1w = (const float*)d_in[13];
    const float* fc1b = (const float*)d_in[14];
    const float* fc2w = (const float*)d_in[15];
    const float* fc2b = (const float*)d_in[16];
    float* out = (float*)d_out;

    cudaFuncSetAttribute(rec_kernel, cudaFuncAttributeMaxDynamicSharedMemorySize, 211072);
    cudaFuncSetAttribute(proj_mid_kernel, cudaFuncAttributeMaxDynamicSharedMemorySize, 98304);

    prep_whh_kernel<<<130, 256>>>(whh0, bih0, bhh0, 0);
    prep_whh_kernel<<<130, 256>>>(whh1, bih1, bhh1, 1);
    prep_whh_kernel<<<130, 256>>>(whh2, bih2, bhh2, 2);
    prep_wih_kernel<<<128, 256>>>(wih1, 0);
    prep_wih_kernel<<<128, 256>>>(wih2, 1);

    proj0_kernel<<<512, 256>>>(x, wih0);
    rec_kernel<<<128, 256, 211072>>>(0, 0);                 // -> g_h0
    proj_mid_kernel<<<dim3(4096, 4), 256, 98304>>>(0);
    rec_kernel<<<128, 256, 211072>>>(1, 1);                 // -> g_h1
    proj_mid_kernel<<<dim3(4096, 4), 256, 98304>>>(1);
    rec_kernel<<<128, 256, 211072>>>(2, 0);                 // -> g_h0
    head_kernel<<<512, 128>>>(fc1w, fc1b, fc2w, fc2b, out);
}

// round 3
// speedup vs baseline: 1.0630x; 1.0630x over previous
#include <cuda_runtime.h>

typedef unsigned long long ull;

#define TT 512
#define BB 512
#define HH 128
#define G4 512

// ---------------- device-global scratch (no allocations allowed) ------------
__device__ __align__(16) float g_xg[134217728];   // [T*B][4H] gate preactivations
__device__ __align__(16) float g_h0[33554432];    // [T*B][H]
__device__ __align__(16) float g_h1[33554432];    // [T*B][H]
__device__ __align__(16) ull   g_wj0[3][256 * 64]; // W_hh cols 0..255 (i,f): [j][k2]
__device__ __align__(16) ull   g_wj1[3][64 * 256]; // W_hh cols 256..511 (g,o): [k2][j-256]
__device__ __align__(16) ull   g_wip[2][64 * 512]; // W_ih layers 1,2: [k2][j]
__device__ float g_bias[3][512];                   // b_ih + b_hh

// ---------------- helpers ---------------------------------------------------
__device__ __forceinline__ void fma2(ull& d, ull a, ull b) {
    asm("fma.rn.f32x2 %0, %1, %2, %0;" : "+l"(d) : "l"(a), "l"(b));
}
__device__ __forceinline__ ull pack2(float a, float b) {
    ull r; asm("mov.b64 %0, {%1,%2};" : "=l"(r) : "f"(a), "f"(b)); return r;
}
__device__ __forceinline__ float sum2(ull v) {
    float lo, hi; asm("mov.b64 {%0,%1}, %2;" : "=f"(lo), "=f"(hi) : "l"(v));
    return lo + hi;
}
__device__ __forceinline__ float sigf(float x) {
    return __fdividef(1.f, 1.f + __expf(-x));
}
__device__ __forceinline__ float tanh_(float x) {
    return 1.f - __fdividef(2.f, 1.f + __expf(2.f * x));
}

// ---------------- fused weight prep (single launch) --------------------------
__global__ void prep_kernel(const float* __restrict__ whh0, const float* __restrict__ whh1,
                            const float* __restrict__ whh2, const float* __restrict__ wih1,
                            const float* __restrict__ wih2,
                            const float* __restrict__ bih0, const float* __restrict__ bhh0,
                            const float* __restrict__ bih1, const float* __restrict__ bhh1,
                            const float* __restrict__ bih2, const float* __restrict__ bhh2) {
    int idx = blockIdx.x * 256 + threadIdx.x;
    if (idx < 98304) {                       // W_hh reorg, 3 layers
        int l = idx >> 15, r = idx & 32767;
        int k2 = r >> 9, j = r & 511;
        const float* w = (l == 0) ? whh0 : (l == 1) ? whh1 : whh2;
        ull p = pack2(w[j * HH + 2 * k2], w[j * HH + 2 * k2 + 1]);
        if (j < 256) g_wj0[l][j * 64 + k2] = p;
        else         g_wj1[l][k2 * 256 + (j - 256)] = p;
    } else if (idx < 163840) {               // W_ih layers 1,2
        int r = idx - 98304;
        int p01 = r >> 15; r &= 32767;
        int k2 = r >> 9, j = r & 511;
        const float* w = p01 ? wih2 : wih1;
        g_wip[p01][k2 * 512 + j] = pack2(w[j * HH + 2 * k2], w[j * HH + 2 * k2 + 1]);
    } else if (idx < 165376) {               // biases
        int r = idx - 163840;
        int l = r >> 9, j = r & 511;
        const float* bi = (l == 0) ? bih0 : (l == 1) ? bih1 : bih2;
        const float* bh = (l == 0) ? bhh0 : (l == 1) ? bhh1 : bhh2;
        g_bias[l][j] = bi[j] + bh[j];
    }
}

// ---------------- layer-0 input projection (K = 8) ---------------------------
__global__ __launch_bounds__(256) void proj0_kernel(const float* __restrict__ x,
                                                    const float* __restrict__ w0) {
    __shared__ float ws[4096], xs[4096], bs[512];
    int t = blockIdx.x, tid = threadIdx.x;
    for (int i = tid; i < 4096; i += 256) ws[i] = w0[i];
    for (int i = tid; i < 512; i += 256) bs[i] = g_bias[0][i];
    for (int i = tid; i < 4096; i += 256) {
        int b = i >> 3, f = i & 7;
        xs[i] = x[(size_t)b * 4096 + t * 8 + f];   // x[b][t][f]
    }
    __syncthreads();
    int j0 = tid, j1 = tid + 256;
    float w0r[8], w1r[8];
#pragma unroll
    for (int f = 0; f < 8; f++) { w0r[f] = ws[j0 * 8 + f]; w1r[f] = ws[j1 * 8 + f]; }
    float bz0 = bs[j0], bz1 = bs[j1];
    float* outt = g_xg + (size_t)t * BB * G4;
    for (int b = 0; b < BB; b++) {
        float a0 = bz0, a1 = bz1;
#pragma unroll
        for (int f = 0; f < 8; f++) {
            float xv = xs[b * 8 + f];
            a0 = fmaf(xv, w0r[f], a0);
            a1 = fmaf(xv, w1r[f], a1);
        }
        outt[(size_t)b * G4 + j0] = a0;
        outt[(size_t)b * G4 + j1] = a1;
    }
}

// ---------------- layers 1,2 input projection: f32x2 tiled GEMM --------------
__global__ __launch_bounds__(256, 2) void proj_mid_kernel(int p) {
    extern __shared__ ull ps[];
    ull* a_s = ps;             // [64 m][64 k2]
    ull* b_s = ps + 64 * 64;   // [64 k2][128 n]
    const float* hin = p ? g_h1 : g_h0;
    const ull* wip = g_wip[p];
    const float* bias = g_bias[p + 1];
    int tid = threadIdx.x;
    int mbase = blockIdx.x * 64;
    int nbase = blockIdx.y * 128;
#pragma unroll
    for (int it = 0; it < 8; it++) {
        int idx = tid + it * 256;
        int row = idx >> 5, k4 = idx & 31;
        float4 v = *(const float4*)(hin + (size_t)(mbase + row) * HH + k4 * 4);
        a_s[row * 64 + 2 * k4]     = pack2(v.x, v.y);
        a_s[row * 64 + 2 * k4 + 1] = pack2(v.z, v.w);
    }
#pragma unroll
    for (int it = 0; it < 32; it++) {
        int idx = tid + it * 256;
        b_s[idx] = wip[(idx >> 7) * G4 + nbase + (idx & 127)];
    }
    __syncthreads();
    int tm = (tid >> 5) * 8, tn = tid & 31;
    ull acc[8][4];
#pragma unroll
    for (int i = 0; i < 8; i++)
#pragma unroll
        for (int j = 0; j < 4; j++) acc[i][j] = 0ull;
#pragma unroll 2
    for (int q = 0; q < 32; q++) {
        ulonglong2 av[8];
#pragma unroll
        for (int i = 0; i < 8; i++)
            av[i] = *(const ulonglong2*)(a_s + (tm + i) * 64 + 2 * q);
        ull bv0[4], bv1[4];
#pragma unroll
        for (int j = 0; j < 4; j++) {
            bv0[j] = b_s[(2 * q) * 128 + tn + 32 * j];
            bv1[j] = b_s[(2 * q + 1) * 128 + tn + 32 * j];
        }
#pragma unroll
        for (int i = 0; i < 8; i++)
#pragma unroll
            for (int j = 0; j < 4; j++) {
                fma2(acc[i][j], av[i].x, bv0[j]);
                fma2(acc[i][j], av[i].y, bv1[j]);
            }
    }
    float bb[4];
#pragma unroll
    for (int j = 0; j < 4; j++) bb[j] = bias[nbase + tn + 32 * j];
#pragma unroll
    for (int i = 0; i < 8; i++) {
        float* rowp = g_xg + (size_t)(mbase + tm + i) * G4 + nbase;
#pragma unroll
        for (int j = 0; j < 4; j++) rowp[tn + 32 * j] = sum2(acc[i][j]) + bb[j];
    }
}

// ---------------- recurrent LSTM layer ---------------------------------------
// 128 CTAs x 256 thr; CTA owns 4 batch rows.
// Gate columns j0 = tid (i,f) live in 128 REGISTERS per thread;
// columns j1 = 256+tid (g,o) live in smem [k2][j] (128 KB). No LDG in loop.
__global__ __launch_bounds__(256, 1) void rec_kernel(int l, int outsel) {
    extern __shared__ char smraw[];
    ull*   wsm = (ull*)smraw;                     // [64][256]  128 KB
    float* hf  = (float*)(smraw + 131072);        // [4][128]     2 KB
    float* gv  = hf + 512;                        // [512][6]    12 KB

    int tid = threadIdx.x;
    int b0 = blockIdx.x * 4;
    float* hout = outsel ? g_h1 : g_h0;

    // smem: g,o columns
    {
        const ulonglong2* src = (const ulonglong2*)g_wj1[l];
        ulonglong2* dst = (ulonglong2*)wsm;
        for (int i = tid; i < 8192; i += 256) dst[i] = src[i];
    }
    // registers: this thread's i/f column (64 k-pairs)
    ull wr[64];
    {
        const ull* src = g_wj0[l] + tid * 64;
#pragma unroll
        for (int k = 0; k < 64; k++) wr[k] = src[k];
    }
    hf[tid] = 0.f; hf[tid + 256] = 0.f;
    int hh = tid & 127, rp = tid >> 7;
    float c0 = 0.f, c1 = 0.f;
    __syncthreads();

    for (int t = 0; t < TT; t++) {
        const float* xrow = g_xg + ((size_t)t * BB + b0) * G4;
        float xa0[4], xa1[4];
#pragma unroll
        for (int r = 0; r < 4; r++) {
            xa0[r] = xrow[r * G4 + tid];
            xa1[r] = xrow[r * G4 + 256 + tid];
        }
        ull acc0[4] = {0, 0, 0, 0}, acc1[4] = {0, 0, 0, 0};
#pragma unroll
        for (int q = 0; q < 32; q++) {
            ulonglong2 hv0 = *(const ulonglong2*)(hf + 0 * HH + 4 * q);
            ulonglong2 hv1 = *(const ulonglong2*)(hf + 1 * HH + 4 * q);
            ulonglong2 hv2 = *(const ulonglong2*)(hf + 2 * HH + 4 * q);
            ulonglong2 hv3 = *(const ulonglong2*)(hf + 3 * HH + 4 * q);
            ull wa1 = wsm[(2 * q) * 256 + tid];
            ull wb1 = wsm[(2 * q + 1) * 256 + tid];
            fma2(acc0[0], hv0.x, wr[2 * q]); fma2(acc0[0], hv0.y, wr[2 * q + 1]);
            fma2(acc0[1], hv1.x, wr[2 * q]); fma2(acc0[1], hv1.y, wr[2 * q + 1]);
            fma2(acc0[2], hv2.x, wr[2 * q]); fma2(acc0[2], hv2.y, wr[2 * q + 1]);
            fma2(acc0[3], hv3.x, wr[2 * q]); fma2(acc0[3], hv3.y, wr[2 * q + 1]);
            fma2(acc1[0], hv0.x, wa1);       fma2(acc1[0], hv0.y, wb1);
            fma2(acc1[1], hv1.x, wa1);       fma2(acc1[1], hv1.y, wb1);
            fma2(acc1[2], hv2.x, wa1);       fma2(acc1[2], hv2.y, wb1);
            fma2(acc1[3], hv3.x, wa1);       fma2(acc1[3], hv3.y, wb1);
        }
#pragma unroll
        for (int r = 0; r < 4; r++) {
            gv[tid * 6 + r]         = sum2(acc0[r]) + xa0[r];
            gv[(256 + tid) * 6 + r] = sum2(acc1[r]) + xa1[r];
        }
        __syncthreads();
        {
            int r0 = rp * 2, r1 = r0 + 1;
            float iv0 = gv[hh * 6 + r0],         iv1 = gv[hh * 6 + r1];
            float fv0 = gv[(128 + hh) * 6 + r0], fv1 = gv[(128 + hh) * 6 + r1];
            float gg0 = gv[(256 + hh) * 6 + r0], gg1 = gv[(256 + hh) * 6 + r1];
            float ov0 = gv[(384 + hh) * 6 + r0], ov1 = gv[(384 + hh) * 6 + r1];
            c0 = sigf(fv0) * c0 + sigf(iv0) * tanh_(gg0);
            c1 = sigf(fv1) * c1 + sigf(iv1) * tanh_(gg1);
            float hn0 = sigf(ov0) * tanh_(c0);
            float hn1 = sigf(ov1) * tanh_(c1);
            hf[r0 * HH + hh] = hn0;
            hf[r1 * HH + hh] = hn1;
            hout[((size_t)t * BB + b0 + r0) * HH + hh] = hn0;
            hout[((size_t)t * BB + b0 + r1) * HH + hh] = hn1;
        }
        __syncthreads();
    }
}

// ---------------- FC head ----------------------------------------------------
__global__ __launch_bounds__(128) void head_kernel(const float* __restrict__ fc1w,
                                                   const float* __restrict__ fc1b,
                                                   const float* __restrict__ fc2w,
                                                   const float* __restrict__ fc2b,
                                                   float* __restrict__ out) {
    __shared__ float last[128], z[128];
    int b = blockIdx.x, tid = threadIdx.x;
    last[tid] = g_h0[((size_t)(TT - 1) * BB + b) * HH + tid];
    __syncthreads();
    float a = fc1b[tid];
#pragma unroll 4
    for (int k = 0; k < HH; k++) a = fmaf(last[k], fc1w[tid * HH + k], a);
    z[tid] = fmaxf(a, 0.f);
    __syncthreads();
    if (tid < 7) {
        float y = fc2b[tid];
#pragma unroll 4
        for (int k = 0; k < HH; k++) y = fmaf(z[k], fc2w[tid * HH + k], y);
        out[b * 7 + tid] = y;
    }
}

// ---------------- launcher ---------------------------------------------------
extern "C" void kernel_launch(void* const* d_in, const int* in_sizes, int n_in,
                              void* d_out, int out_size) {
    (void)in_sizes; (void)n_in; (void)out_size;
    const float* x    = (const float*)d_in[0];
    const float* wih0 = (const float*)d_in[1];
    const float* whh0 = (const float*)d_in[2];
    const float* bih0 = (const float*)d_in[3];
    const float* bhh0 = (const float*)d_in[4];
    const float* wih1 = (const float*)d_in[5];
    const float* whh1 = (const float*)d_in[6];
    const float* bih1 = (const float*)d_in[7];
    const float* bhh1 = (const float*)d_in[8];
    const float* wih2 = (const float*)d_in[9];
    const float* whh2 = (const float*)d_in[10];
    const float* bih2 = (const float*)d_in[11];
    const float* bhh2 = (const float*)d_in[12];
    const float* fc1w = (const float*)d_in[13];
    const float* fc1b = (const float*)d_in[14];
    const float* fc2w = (const float*)d_in[15];
    const float* fc2b = (const float*)d_in[16];
    float* out = (float*)d_out;

    cudaFuncSetAttribute(rec_kernel, cudaFuncAttributeMaxDynamicSharedMemorySize, 145408);
    cudaFuncSetAttribute(proj_mid_kernel, cudaFuncAttributeMaxDynamicSharedMemorySize, 98304);

    prep_kernel<<<647, 256>>>(whh0, whh1, whh2, wih1, wih2,
                              bih0, bhh0, bih1, bhh1, bih2, bhh2);   // launch 1
    proj0_kernel<<<512, 256>>>(x, wih0);                              // launch 2
    rec_kernel<<<128, 256, 145408>>>(0, 0);                           // launch 3 -> g_h0
    proj_mid_kernel<<<dim3(4096, 4), 256, 98304>>>(0);                // launch 4
    rec_kernel<<<128, 256, 145408>>>(1, 1);                           // launch 5 -> g_h1  (ncu target)
    proj_mid_kernel<<<dim3(4096, 4), 256, 98304>>>(1);                // launch 6
    rec_kernel<<<128, 256, 145408>>>(2, 0);                           // launch 7 -> g_h0
    head_kernel<<<512, 128>>>(fc1w, fc1b, fc2w, fc2b, out);           // launch 8
}

// round 4
// speedup vs baseline: 1.2030x; 1.1317x over previous
#include <cuda_runtime.h>

typedef unsigned long long ull;

#define TT 512
#define BB 512
#define HH 128
#define G4 512

// ---------------- device-global scratch (no allocations allowed) ------------
__device__ __align__(16) float g_xg[134217728];    // [T*B][4H] gate preactivations
__device__ __align__(16) float g_h0[33554432];     // [T*B][H]
__device__ __align__(16) float g_h1[33554432];     // [T*B][H]
__device__ __align__(16) ull   g_wj0[3][256 * 64]; // W_hh cols 0..255 (i,f): [j][k2]
__device__ __align__(16) ull   g_wj1[3][32 * 256 * 2]; // W_hh cols 256..511 (g,o): [q][col][2]
__device__ __align__(16) ull   g_wip[2][64 * 512]; // W_ih layers 1,2: [k2][j]
__device__ float g_bias[3][512];                   // b_ih + b_hh

// ---------------- helpers ---------------------------------------------------
__device__ __forceinline__ void fma2(ull& d, ull a, ull b) {
    asm("fma.rn.f32x2 %0, %1, %2, %0;" : "+l"(d) : "l"(a), "l"(b));
}
__device__ __forceinline__ ull pack2(float a, float b) {
    ull r; asm("mov.b64 %0, {%1,%2};" : "=l"(r) : "f"(a), "f"(b)); return r;
}
__device__ __forceinline__ float sum2(ull v) {
    float lo, hi; asm("mov.b64 {%0,%1}, %2;" : "=f"(lo), "=f"(hi) : "l"(v));
    return lo + hi;
}
__device__ __forceinline__ float sigf(float x) {
    return __fdividef(1.f, 1.f + __expf(-x));
}
__device__ __forceinline__ float tanh_(float x) {
    return 1.f - __fdividef(2.f, 1.f + __expf(2.f * x));
}

// ---------------- weight prep (2 launches so rec is launch #4) ---------------
__global__ void prep_a_kernel(const float* __restrict__ whh0, const float* __restrict__ whh1,
                              const float* __restrict__ whh2,
                              const float* __restrict__ bih0, const float* __restrict__ bhh0,
                              const float* __restrict__ bih1, const float* __restrict__ bhh1,
                              const float* __restrict__ bih2, const float* __restrict__ bhh2) {
    int idx = blockIdx.x * 256 + threadIdx.x;
    if (idx < 98304) {                       // W_hh reorg, 3 layers
        int l = idx >> 15, r = idx & 32767;
        int k2 = r >> 9, j = r & 511;
        const float* w = (l == 0) ? whh0 : (l == 1) ? whh1 : whh2;
        ull p = pack2(w[j * HH + 2 * k2], w[j * HH + 2 * k2 + 1]);
        if (j < 256) g_wj0[l][j * 64 + k2] = p;
        else         g_wj1[l][((k2 >> 1) * 256 + (j - 256)) * 2 + (k2 & 1)] = p;
    } else if (idx < 99840) {                // biases
        int r = idx - 98304;
        int l = r >> 9, j = r & 511;
        const float* bi = (l == 0) ? bih0 : (l == 1) ? bih1 : bih2;
        const float* bh = (l == 0) ? bhh0 : (l == 1) ? bhh1 : bhh2;
        g_bias[l][j] = bi[j] + bh[j];
    }
}

__global__ void prep_b_kernel(const float* __restrict__ wih1, const float* __restrict__ wih2) {
    int idx = blockIdx.x * 256 + threadIdx.x;
    if (idx < 65536) {
        int p01 = idx >> 15, r = idx & 32767;
        int k2 = r >> 9, j = r & 511;
        const float* w = p01 ? wih2 : wih1;
        g_wip[p01][k2 * 512 + j] = pack2(w[j * HH + 2 * k2], w[j * HH + 2 * k2 + 1]);
    }
}

// ---------------- layer-0 input projection (K = 8) ---------------------------
__global__ __launch_bounds__(256) void proj0_kernel(const float* __restrict__ x,
                                                    const float* __restrict__ w0) {
    __shared__ float ws[4096], xs[4096], bs[512];
    int t = blockIdx.x, tid = threadIdx.x;
    for (int i = tid; i < 4096; i += 256) ws[i] = w0[i];
    for (int i = tid; i < 512; i += 256) bs[i] = g_bias[0][i];
    for (int i = tid; i < 4096; i += 256) {
        int b = i >> 3, f = i & 7;
        xs[i] = x[(size_t)b * 4096 + t * 8 + f];   // x[b][t][f]
    }
    __syncthreads();
    int j0 = tid, j1 = tid + 256;
    float w0r[8], w1r[8];
#pragma unroll
    for (int f = 0; f < 8; f++) { w0r[f] = ws[j0 * 8 + f]; w1r[f] = ws[j1 * 8 + f]; }
    float bz0 = bs[j0], bz1 = bs[j1];
    float* outt = g_xg + (size_t)t * BB * G4;
    for (int b = 0; b < BB; b++) {
        float a0 = bz0, a1 = bz1;
#pragma unroll
        for (int f = 0; f < 8; f++) {
            float xv = xs[b * 8 + f];
            a0 = fmaf(xv, w0r[f], a0);
            a1 = fmaf(xv, w1r[f], a1);
        }
        outt[(size_t)b * G4 + j0] = a0;
        outt[(size_t)b * G4 + j1] = a1;
    }
}

// ---------------- layers 1,2 input projection: f32x2 tiled GEMM --------------
// (at its FFMA2-rt3 floor; unchanged)
__global__ __launch_bounds__(256, 2) void proj_mid_kernel(int p) {
    extern __shared__ ull ps[];
    ull* a_s = ps;             // [64 m][64 k2]
    ull* b_s = ps + 64 * 64;   // [64 k2][128 n]
    const float* hin = p ? g_h1 : g_h0;
    const ull* wip = g_wip[p];
    const float* bias = g_bias[p + 1];
    int tid = threadIdx.x;
    int mbase = blockIdx.x * 64;
    int nbase = blockIdx.y * 128;
#pragma unroll
    for (int it = 0; it < 8; it++) {
        int idx = tid + it * 256;
        int row = idx >> 5, k4 = idx & 31;
        float4 v = *(const float4*)(hin + (size_t)(mbase + row) * HH + k4 * 4);
        a_s[row * 64 + 2 * k4]     = pack2(v.x, v.y);
        a_s[row * 64 + 2 * k4 + 1] = pack2(v.z, v.w);
    }
#pragma unroll
    for (int it = 0; it < 32; it++) {
        int idx = tid + it * 256;
        b_s[idx] = wip[(idx >> 7) * G4 + nbase + (idx & 127)];
    }
    __syncthreads();
    int tm = (tid >> 5) * 8, tn = tid & 31;
    ull acc[8][4];
#pragma unroll
    for (int i = 0; i < 8; i++)
#pragma unroll
        for (int j = 0; j < 4; j++) acc[i][j] = 0ull;
#pragma unroll 2
    for (int q = 0; q < 32; q++) {
        ulonglong2 av[8];
#pragma unroll
        for (int i = 0; i < 8; i++)
            av[i] = *(const ulonglong2*)(a_s + (tm + i) * 64 + 2 * q);
        ull bv0[4], bv1[4];
#pragma unroll
        for (int j = 0; j < 4; j++) {
            bv0[j] = b_s[(2 * q) * 128 + tn + 32 * j];
            bv1[j] = b_s[(2 * q + 1) * 128 + tn + 32 * j];
        }
#pragma unroll
        for (int i = 0; i < 8; i++)
#pragma unroll
            for (int j = 0; j < 4; j++) {
                fma2(acc[i][j], av[i].x, bv0[j]);
                fma2(acc[i][j], av[i].y, bv1[j]);
            }
    }
    float bb[4];
#pragma unroll
    for (int j = 0; j < 4; j++) bb[j] = bias[nbase + tn + 32 * j];
#pragma unroll
    for (int i = 0; i < 8; i++) {
        float* rowp = g_xg + (size_t)(mbase + tm + i) * G4 + nbase;
#pragma unroll
        for (int j = 0; j < 4; j++) rowp[tn + 32 * j] = sum2(acc[i][j]) + bb[j];
    }
}

// ---------------- recurrent LSTM layer ---------------------------------------
// 128 CTAs x 256 thr; CTA owns 4 batch rows.
// Gate-column map: lane = 16-group; thread (wid, lane) owns
//   j0 = 16*wid + (lane&15) + 128*(lane>>4)   (gate i for lo-lanes, f for hi)
//   j1 = j0 + 256                             (gate g for lo-lanes, o for hi)
// j0 column weights in 128 registers, j1 column in smem (paired k2 layout).
// Cross-gate exchange via shfl.xor(16) -> ONE barrier per step (h double-buffered).
__global__ __launch_bounds__(256, 1) void rec_kernel(int l, int outsel) {
    extern __shared__ char smraw[];
    ull*   wsm = (ull*)smraw;                     // [32 q][256 col][2]  128 KB
    float* hfb = (float*)(smraw + 131072);        // 2 x [4][128]          4 KB

    int tid = threadIdx.x;
    int lane = tid & 31, wid = tid >> 5;
    int sub = lane & 15, hi = lane >> 4;
    int hh = (wid << 4) + sub;                    // 0..127
    int j0 = hh + (hi << 7);                      // 0..255
    int j1 = j0 + 256;
    int b0 = blockIdx.x * 4;
    float* hout = outsel ? g_h1 : g_h0;

    {   // smem: g,o column weights (paired)
        const ulonglong2* src = (const ulonglong2*)g_wj1[l];
        ulonglong2* dst = (ulonglong2*)wsm;
        for (int i = tid; i < 8192; i += 256) dst[i] = src[i];
    }
    ull wr[64];                                   // this thread's i/f column
    {
        const ull* src = g_wj0[l] + j0 * 64;
#pragma unroll
        for (int k = 0; k < 64; k++) wr[k] = src[k];
    }
    hfb[tid] = 0.f; hfb[tid + 256] = 0.f;         // zero buffer 0
    float cA = 0.f, cB = 0.f;
    int rowA = hi ? 2 : 0, rowB = hi ? 3 : 1;     // rows this thread finalizes
    int ra = hi ? 0 : 2;                          // rows whose gates it sends
    __syncthreads();

    for (int t = 0; t < TT; t++) {
        const float* hcur = hfb + ((t & 1) << 9);
        float* hnxt = hfb + (((t + 1) & 1) << 9);
        const float* xrow = g_xg + ((size_t)t * BB + b0) * G4;
        float xa0[4], xa1[4];
#pragma unroll
        for (int r = 0; r < 4; r++) {
            xa0[r] = xrow[r * G4 + j0];
            xa1[r] = xrow[r * G4 + j1];
        }
        ull acc0[4] = {0, 0, 0, 0}, acc1[4] = {0, 0, 0, 0};
#pragma unroll
        for (int q = 0; q < 32; q++) {
            ulonglong2 hv0 = *(const ulonglong2*)(hcur + 0 * HH + 4 * q);
            ulonglong2 hv1 = *(const ulonglong2*)(hcur + 1 * HH + 4 * q);
            ulonglong2 hv2 = *(const ulonglong2*)(hcur + 2 * HH + 4 * q);
            ulonglong2 hv3 = *(const ulonglong2*)(hcur + 3 * HH + 4 * q);
            ulonglong2 wp = *(const ulonglong2*)(wsm + (q * 256 + j0) * 2);
            fma2(acc0[0], hv0.x, wr[2 * q]); fma2(acc0[0], hv0.y, wr[2 * q + 1]);
            fma2(acc0[1], hv1.x, wr[2 * q]); fma2(acc0[1], hv1.y, wr[2 * q + 1]);
            fma2(acc0[2], hv2.x, wr[2 * q]); fma2(acc0[2], hv2.y, wr[2 * q + 1]);
            fma2(acc0[3], hv3.x, wr[2 * q]); fma2(acc0[3], hv3.y, wr[2 * q + 1]);
            fma2(acc1[0], hv0.x, wp.x);      fma2(acc1[0], hv0.y, wp.y);
            fma2(acc1[1], hv1.x, wp.x);      fma2(acc1[1], hv1.y, wp.y);
            fma2(acc1[2], hv2.x, wp.x);      fma2(acc1[2], hv2.y, wp.y);
            fma2(acc1[3], hv3.x, wp.x);      fma2(acc1[3], hv3.y, wp.y);
        }
        float s0[4], s1[4];
#pragma unroll
        for (int r = 0; r < 4; r++) {
            s0[r] = sum2(acc0[r]) + xa0[r];
            s1[r] = sum2(acc1[r]) + xa1[r];
        }
        // exchange gates with lane^16 partner (4 shuffles)
        float rv0 = __shfl_xor_sync(0xFFFFFFFFu, s0[ra],     16);
        float rv1 = __shfl_xor_sync(0xFFFFFFFFu, s0[ra + 1], 16);
        float rv2 = __shfl_xor_sync(0xFFFFFFFFu, s1[ra],     16);
        float rv3 = __shfl_xor_sync(0xFFFFFFFFu, s1[ra + 1], 16);
        float iA = hi ? rv0 : s0[rowA], iB = hi ? rv1 : s0[rowB];
        float gA = hi ? rv2 : s1[rowA], gB = hi ? rv3 : s1[rowB];
        float fA = hi ? s0[rowA] : rv0, fB = hi ? s0[rowB] : rv1;
        float oA = hi ? s1[rowA] : rv2, oB = hi ? s1[rowB] : rv3;
        cA = sigf(fA) * cA + sigf(iA) * tanh_(gA);
        cB = sigf(fB) * cB + sigf(iB) * tanh_(gB);
        float hA = sigf(oA) * tanh_(cA);
        float hB = sigf(oB) * tanh_(cB);
        hnxt[rowA * HH + hh] = hA;
        hnxt[rowB * HH + hh] = hB;
        hout[((size_t)t * BB + b0 + rowA) * HH + hh] = hA;
        hout[((size_t)t * BB + b0 + rowB) * HH + hh] = hB;
        __syncthreads();
    }
}

// ---------------- FC head ----------------------------------------------------
__global__ __launch_bounds__(128) void head_kernel(const float* __restrict__ fc1w,
                                                   const float* __restrict__ fc1b,
                                                   const float* __restrict__ fc2w,
                                                   const float* __restrict__ fc2b,
                                                   float* __restrict__ out) {
    __shared__ float last[128], z[128];
    int b = blockIdx.x, tid = threadIdx.x;
    last[tid] = g_h0[((size_t)(TT - 1) * BB + b) * HH + tid];
    __syncthreads();
    float a = fc1b[tid];
#pragma unroll 4
    for (int k = 0; k < HH; k++) a = fmaf(last[k], fc1w[tid * HH + k], a);
    z[tid] = fmaxf(a, 0.f);
    __syncthreads();
    if (tid < 7) {
        float y = fc2b[tid];
#pragma unroll 4
        for (int k = 0; k < HH; k++) y = fmaf(z[k], fc2w[tid * HH + k], y);
        out[b * 7 + tid] = y;
    }
}

// ---------------- launcher ---------------------------------------------------
extern "C" void kernel_launch(void* const* d_in, const int* in_sizes, int n_in,
                              void* d_out, int out_size) {
    (void)in_sizes; (void)n_in; (void)out_size;
    const float* x    = (const float*)d_in[0];
    const float* wih0 = (const float*)d_in[1];
    const float* whh0 = (const float*)d_in[2];
    const float* bih0 = (const float*)d_in[3];
    const float* bhh0 = (const float*)d_in[4];
    const float* wih1 = (const float*)d_in[5];
    const float* whh1 = (const float*)d_in[6];
    const float* bih1 = (const float*)d_in[7];
    const float* bhh1 = (const float*)d_in[8];
    const float* wih2 = (const float*)d_in[9];
    const float* whh2 = (const float*)d_in[10];
    const float* bih2 = (const float*)d_in[11];
    const float* bhh2 = (const float*)d_in[12];
    const float* fc1w = (const float*)d_in[13];
    const float* fc1b = (const float*)d_in[14];
    const float* fc2w = (const float*)d_in[15];
    const float* fc2b = (const float*)d_in[16];
    float* out = (float*)d_out;

    cudaFuncSetAttribute(rec_kernel, cudaFuncAttributeMaxDynamicSharedMemorySize, 135168);
    cudaFuncSetAttribute(proj_mid_kernel, cudaFuncAttributeMaxDynamicSharedMemorySize, 98304);

    prep_a_kernel<<<390, 256>>>(whh0, whh1, whh2,
                                bih0, bhh0, bih1, bhh1, bih2, bhh2);  // launch 1
    prep_b_kernel<<<256, 256>>>(wih1, wih2);                          // launch 2
    proj0_kernel<<<512, 256>>>(x, wih0);                              // launch 3
    rec_kernel<<<128, 256, 135168>>>(0, 0);                           // launch 4 -> g_h0 (ncu target)
    proj_mid_kernel<<<dim3(4096, 4), 256, 98304>>>(0);                // launch 5
    rec_kernel<<<128, 256, 135168>>>(1, 1);                           // launch 6 -> g_h1
    proj_mid_kernel<<<dim3(4096, 4), 256, 98304>>>(1);                // launch 7
    rec_kernel<<<128, 256, 135168>>>(2, 0);                           // launch 8 -> g_h0
    head_kernel<<<512, 128>>>(fc1w, fc1b, fc2w, fc2b, out);           // launch 9
}

// round 6
// speedup vs baseline: 1.2788x; 1.0630x over previous
#include <cuda_runtime.h>
#include <cuda_bf16.h>
#include <cstdint>

typedef unsigned long long ull;

#define TT 512
#define BB 512
#define HH 128
#define G4 512
#define MTOT 262144              // T*B

// ---------------- device-global scratch (no allocations allowed) ------------
__device__ __align__(16) float g_xg[134217728];    // [512 j][262144 m] gate preacts (gate-major)
__device__ __align__(16) float g_h0[33554432];     // [m][H]
__device__ __align__(16) float g_h1[33554432];     // [m][H]
__device__ __align__(16) ull   g_wj0[3][256 * 64]; // W_hh cols 0..255 (i,f): [j][k2]
__device__ __align__(16) ull   g_wj1[3][32 * 256 * 2]; // W_hh cols 256..511 (g,o): [q][col][2]
__device__ __align__(16) uint32_t g_wmma[2][4][16384]; // W_ih l1,l2: [ntile128][hi 8192|lo 8192] frag-order words
__device__ float g_bias[3][512];                   // b_ih + b_hh

// ---------------- helpers ---------------------------------------------------
__device__ __forceinline__ void fma2(ull& d, ull a, ull b) {
    asm("fma.rn.f32x2 %0, %1, %2, %0;" : "+l"(d) : "l"(a), "l"(b));
}
__device__ __forceinline__ ull pack2(float a, float b) {
    ull r; asm("mov.b64 %0, {%1,%2};" : "=l"(r) : "f"(a), "f"(b)); return r;
}
__device__ __forceinline__ float sum2(ull v) {
    float lo, hi; asm("mov.b64 {%0,%1}, %2;" : "=f"(lo), "=f"(hi) : "l"(v));
    return lo + hi;
}
__device__ __forceinline__ float sigf(float x) {
    return __fdividef(1.f, 1.f + __expf(-x));
}
__device__ __forceinline__ float tanh_(float x) {
    return 1.f - __fdividef(2.f, 1.f + __expf(2.f * x));
}
__device__ __forceinline__ uint32_t packbf(float x, float y) {
    __nv_bfloat162 t = __floats2bfloat162_rn(x, y);
    return *(uint32_t*)&t;
}
__device__ __forceinline__ void mma_bf16(float* d, const uint32_t* a, const uint32_t* b) {
    asm volatile(
        "mma.sync.aligned.m16n8k16.row.col.f32.bf16.bf16.f32 "
        "{%0,%1,%2,%3}, {%4,%5,%6,%7}, {%8,%9}, {%0,%1,%2,%3};"
        : "+f"(d[0]), "+f"(d[1]), "+f"(d[2]), "+f"(d[3])
        : "r"(a[0]), "r"(a[1]), "r"(a[2]), "r"(a[3]), "r"(b[0]), "r"(b[1]));
}

// ---------------- weight prep A: W_hh reorg + biases -------------------------
__global__ void prep_a_kernel(const float* __restrict__ whh0, const float* __restrict__ whh1,
                              const float* __restrict__ whh2,
                              const float* __restrict__ bih0, const float* __restrict__ bhh0,
                              const float* __restrict__ bih1, const float* __restrict__ bhh1,
                              const float* __restrict__ bih2, const float* __restrict__ bhh2) {
    int idx = blockIdx.x * 256 + threadIdx.x;
    if (idx < 98304) {
        int l = idx >> 15, r = idx & 32767;
        int k2 = r >> 9, j = r & 511;
        const float* w = (l == 0) ? whh0 : (l == 1) ? whh1 : whh2;
        ull p = pack2(w[j * HH + 2 * k2], w[j * HH + 2 * k2 + 1]);
        if (j < 256) g_wj0[l][j * 64 + k2] = p;
        else         g_wj1[l][((k2 >> 1) * 256 + (j - 256)) * 2 + (k2 & 1)] = p;
    } else if (idx < 99840) {
        int r = idx - 98304;
        int l = r >> 9, j = r & 511;
        const float* bi = (l == 0) ? bih0 : (l == 1) ? bih1 : bih2;
        const float* bh = (l == 0) ? bhh0 : (l == 1) ? bhh1 : bhh2;
        g_bias[l][j] = bi[j] + bh[j];
    }
}

// ---------------- weight prep B: W_ih (l1,l2) -> bf16 hi/lo fragment order ---
// B fragment layout (m16n8k16 col-major B): b0 = Bw[n][w], b1 = Bw[n][w+4],
// n = lane>>2, w = lane&3, Bw = bf16x2 words over k. Stored as
// [kt][ntt][lane][reg] words so the GEMM loads one lds.64 per n8-tile.
__global__ void prep_b_kernel(const float* __restrict__ wih1, const float* __restrict__ wih2) {
    int idx = blockIdx.x * 256 + threadIdx.x;
    if (idx >= 65536) return;
    int p = idx >> 15, r2 = idx & 32767;
    int j = r2 >> 6, kw = r2 & 63;
    const float* w = p ? wih2 : wih1;
    float2 v = *(const float2*)(w + j * HH + 2 * kw);
    float xh = __bfloat162float(__float2bfloat16(v.x));
    float yh = __bfloat162float(__float2bfloat16(v.y));
    uint32_t wh = packbf(v.x, v.y);
    uint32_t wl = packbf(v.x - xh, v.y - yh);
    int ntile = j >> 7, n = j & 127;
    int ntt = n >> 3, nr = n & 7;
    int kt = kw >> 3, wi = kw & 7, w3 = wi & 3, reg = wi >> 2;
    uint32_t dst = (uint32_t)(((kt * 16 + ntt) * 32 + nr * 4 + w3) * 2 + reg);
    g_wmma[p][ntile][dst] = wh;
    g_wmma[p][ntile][8192 + dst] = wl;
}

// ---------------- layer-0 input projection (K = 8), gate-major output --------
__global__ __launch_bounds__(256) void proj0_kernel(const float* __restrict__ x,
                                                    const float* __restrict__ w0) {
    __shared__ float ws[4096], bsm[512];
    int t = blockIdx.x, tid = threadIdx.x;
    for (int i = tid; i < 4096; i += 256) ws[i] = w0[i];
    for (int i = tid; i < 512; i += 256) bsm[i] = g_bias[0][i];
    __syncthreads();
    int b1 = tid, b2 = tid + 256;
    float4 x1a = *(const float4*)(x + (size_t)b1 * 4096 + t * 8);
    float4 x1b = *(const float4*)(x + (size_t)b1 * 4096 + t * 8 + 4);
    float4 x2a = *(const float4*)(x + (size_t)b2 * 4096 + t * 8);
    float4 x2b = *(const float4*)(x + (size_t)b2 * 4096 + t * 8 + 4);
#pragma unroll 4
    for (int j = 0; j < 512; j++) {
        float4 wa = *(const float4*)(ws + j * 8);
        float4 wb = *(const float4*)(ws + j * 8 + 4);
        float a1 = bsm[j], a2 = bsm[j];
        a1 = fmaf(x1a.x, wa.x, a1); a1 = fmaf(x1a.y, wa.y, a1);
        a1 = fmaf(x1a.z, wa.z, a1); a1 = fmaf(x1a.w, wa.w, a1);
        a1 = fmaf(x1b.x, wb.x, a1); a1 = fmaf(x1b.y, wb.y, a1);
        a1 = fmaf(x1b.z, wb.z, a1); a1 = fmaf(x1b.w, wb.w, a1);
        a2 = fmaf(x2a.x, wa.x, a2); a2 = fmaf(x2a.y, wa.y, a2);
        a2 = fmaf(x2a.z, wa.z, a2); a2 = fmaf(x2a.w, wa.w, a2);
        a2 = fmaf(x2b.x, wb.x, a2); a2 = fmaf(x2b.y, wb.y, a2);
        a2 = fmaf(x2b.z, wb.z, a2); a2 = fmaf(x2b.w, wb.w, a2);
        g_xg[(size_t)j * MTOT + t * 512 + b1] = a1;
        g_xg[(size_t)j * MTOT + t * 512 + b2] = a2;
    }
}

// ---------------- layers 1,2 input projection: mma.sync bf16 3-split GEMM ----
// CTA tile 128m x 128n, K=128. 8 warps = 4 m-warps x 2 n-halves; warp 32m x 64n.
// A fragment layout (m16k16): a0=(r,w) a1=(r+8,w) a2=(r,w+4) a3=(r+8,w+4),
// r=lane>>2, w=lane&3 (bf16x2 words over k). Stored [mtile][kt][lane][reg].
// smem words: A_hi[8192] | A_lo[8192] | B_hi[8192] | B_lo[8192] | bias f32[128]
#define ALO_W 8192
#define BHI_W 16384
#define BLO_W 24576
#define SMW_TOT (32768 * 4 + 512)

__global__ __launch_bounds__(256, 1) void proj_mma_kernel(int p) {
    extern __shared__ uint32_t smw[];
    float* bias = (float*)(smw + 32768);
    int tid = threadIdx.x;
    int wid = tid >> 5, lane = tid & 31;
    int mw = wid & 3, nh = wid >> 2;
    const float* hin = p ? g_h1 : g_h0;
    int mbase = blockIdx.x * 128;
    int nbase = blockIdx.y * 128;

    // A: load h rows (fp32), split hi/lo bf16 into fragment-order smem
#pragma unroll
    for (int it = 0; it < 32; it++) {
        int idx = it * 256 + tid;
        int m = idx >> 6, kw = idx & 63;
        float2 v = *(const float2*)(hin + (size_t)(mbase + m) * HH + 2 * kw);
        float xh = __bfloat162float(__float2bfloat16(v.x));
        float yh = __bfloat162float(__float2bfloat16(v.y));
        uint32_t whw = packbf(v.x, v.y);
        uint32_t wlw = packbf(v.x - xh, v.y - yh);
        int mt = m >> 4, row = m & 15, half = row >> 3, r = row & 7;
        int kt = kw >> 3, wi = kw & 7, w3 = wi & 3, wh2 = wi >> 2;
        uint32_t dst = (uint32_t)(((mt * 8 + kt) * 32 + r * 4 + w3) * 4 + half + 2 * wh2);
        smw[dst] = whw;
        smw[ALO_W + dst] = wlw;
    }
    // B: straight copy of prepped fragment-order hi+lo (64 KB)
    {
        const uint4* src = (const uint4*)g_wmma[p][blockIdx.y];
        uint4* dst = (uint4*)(smw + BHI_W);
#pragma unroll
        for (int it = 0; it < 16; it++) dst[it * 256 + tid] = src[it * 256 + tid];
    }
    if (tid < 128) bias[tid] = g_bias[p + 1][nbase + tid];
    __syncthreads();

    float acc[2][8][4];
#pragma unroll
    for (int mt = 0; mt < 2; mt++)
#pragma unroll
        for (int nt = 0; nt < 8; nt++)
#pragma unroll
            for (int i = 0; i < 4; i++) acc[mt][nt][i] = 0.f;

#pragma unroll
    for (int kt = 0; kt < 8; kt++) {
        uint4 ah[2], al[2];
#pragma unroll
        for (int mt = 0; mt < 2; mt++) {
            int mtile = mw * 2 + mt;
            ah[mt] = *((const uint4*)smw + ((mtile * 8 + kt) * 32 + lane));
            al[mt] = *((const uint4*)(smw + ALO_W) + ((mtile * 8 + kt) * 32 + lane));
        }
        uint2 bh[8], bl[8];
#pragma unroll
        for (int nt = 0; nt < 8; nt++) {
            int ntt = nh * 8 + nt;
            bh[nt] = *((const uint2*)(smw + BHI_W) + ((kt * 16 + ntt) * 32 + lane));
            bl[nt] = *((const uint2*)(smw + BLO_W) + ((kt * 16 + ntt) * 32 + lane));
        }
#pragma unroll
        for (int mt = 0; mt < 2; mt++)
#pragma unroll
            for (int nt = 0; nt < 8; nt++) {
                mma_bf16(acc[mt][nt], (const uint32_t*)&ah[mt], (const uint32_t*)&bh[nt]);
                mma_bf16(acc[mt][nt], (const uint32_t*)&al[mt], (const uint32_t*)&bh[nt]);
                mma_bf16(acc[mt][nt], (const uint32_t*)&ah[mt], (const uint32_t*)&bl[nt]);
            }
    }

    // epilogue: +bias, gate-major coalesced-sector STG
    int r = lane >> 2, cc = lane & 3;
#pragma unroll
    for (int mt = 0; mt < 2; mt++) {
        int m0 = mbase + mw * 32 + mt * 16 + r;
#pragma unroll
        for (int nt = 0; nt < 8; nt++) {
            int nl = nh * 64 + nt * 8 + 2 * cc;
            size_t base = (size_t)(nbase + nl) * MTOT + m0;
            float b0v = bias[nl], b1v = bias[nl + 1];
            g_xg[base]            = acc[mt][nt][0] + b0v;
            g_xg[base + MTOT]     = acc[mt][nt][1] + b1v;
            g_xg[base + 8]        = acc[mt][nt][2] + b0v;
            g_xg[base + MTOT + 8] = acc[mt][nt][3] + b1v;
        }
    }
}

// ---------------- recurrent LSTM layer ---------------------------------------
__global__ __launch_bounds__(256, 1) void rec_kernel(int l, int outsel) {
    extern __shared__ char smraw[];
    ull*   wsm = (ull*)smraw;                     // [32 q][256 col][2]  128 KB
    float* hfb = (float*)(smraw + 131072);        // 2 x [4][128]          4 KB

    int tid = threadIdx.x;
    int lane = tid & 31, wid = tid >> 5;
    int sub = lane & 15, hi = lane >> 4;
    int hh = (wid << 4) + sub;
    int j0 = hh + (hi << 7);
    int j1 = j0 + 256;
    int b0 = blockIdx.x * 4;
    float* hout = outsel ? g_h1 : g_h0;

    {
        const ulonglong2* src = (const ulonglong2*)g_wj1[l];
        ulonglong2* dst = (ulonglong2*)wsm;
        for (int i = tid; i < 8192; i += 256) dst[i] = src[i];
    }
    ull wr[64];
    {
        const ull* src = g_wj0[l] + j0 * 64;
#pragma unroll
        for (int k = 0; k < 64; k++) wr[k] = src[k];
    }
    hfb[tid] = 0.f; hfb[tid + 256] = 0.f;
    float cA = 0.f, cB = 0.f;
    int rowA = hi ? 2 : 0, rowB = hi ? 3 : 1;
    int ra = hi ? 0 : 2;
    const float* xg0 = g_xg + (size_t)j0 * MTOT + b0;
    const float* xg1 = g_xg + (size_t)j1 * MTOT + b0;
    __syncthreads();

    for (int t = 0; t < TT; t++) {
        const float* hcur = hfb + ((t & 1) << 9);
        float* hnxt = hfb + (((t + 1) & 1) << 9);
        float4 xa0 = *(const float4*)(xg0 + t * 512);
        float4 xa1 = *(const float4*)(xg1 + t * 512);
        ull acc0[4] = {0, 0, 0, 0}, acc1[4] = {0, 0, 0, 0};
#pragma unroll
        for (int q = 0; q < 32; q++) {
            ulonglong2 hv0 = *(const ulonglong2*)(hcur + 0 * HH + 4 * q);
            ulonglong2 hv1 = *(const ulonglong2*)(hcur + 1 * HH + 4 * q);
            ulonglong2 hv2 = *(const ulonglong2*)(hcur + 2 * HH + 4 * q);
            ulonglong2 hv3 = *(const ulonglong2*)(hcur + 3 * HH + 4 * q);
            ulonglong2 wp = *(const ulonglong2*)(wsm + (q * 256 + j0) * 2);
            fma2(acc0[0], hv0.x, wr[2 * q]); fma2(acc0[0], hv0.y, wr[2 * q + 1]);
            fma2(acc0[1], hv1.x, wr[2 * q]); fma2(acc0[1], hv1.y, wr[2 * q + 1]);
            fma2(acc0[2], hv2.x, wr[2 * q]); fma2(acc0[2], hv2.y, wr[2 * q + 1]);
            fma2(acc0[3], hv3.x, wr[2 * q]); fma2(acc0[3], hv3.y, wr[2 * q + 1]);
            fma2(acc1[0], hv0.x, wp.x);      fma2(acc1[0], hv0.y, wp.y);
            fma2(acc1[1], hv1.x, wp.x);      fma2(acc1[1], hv1.y, wp.y);
            fma2(acc1[2], hv2.x, wp.x);      fma2(acc1[2], hv2.y, wp.y);
            fma2(acc1[3], hv3.x, wp.x);      fma2(acc1[3], hv3.y, wp.y);
        }
        float s0[4], s1[4];
        s0[0] = sum2(acc0[0]) + xa0.x; s0[1] = sum2(acc0[1]) + xa0.y;
        s0[2] = sum2(acc0[2]) + xa0.z; s0[3] = sum2(acc0[3]) + xa0.w;
        s1[0] = sum2(acc1[0]) + xa1.x; s1[1] = sum2(acc1[1]) + xa1.y;
        s1[2] = sum2(acc1[2]) + xa1.z; s1[3] = sum2(acc1[3]) + xa1.w;
        float rv0 = __shfl_xor_sync(0xFFFFFFFFu, s0[ra],     16);
        float rv1 = __shfl_xor_sync(0xFFFFFFFFu, s0[ra + 1], 16);
        float rv2 = __shfl_xor_sync(0xFFFFFFFFu, s1[ra],     16);
        float rv3 = __shfl_xor_sync(0xFFFFFFFFu, s1[ra + 1], 16);
        float iA = hi ? rv0 : s0[rowA], iB = hi ? rv1 : s0[rowB];
        float gA = hi ? rv2 : s1[rowA], gB = hi ? rv3 : s1[rowB];
        float fA = hi ? s0[rowA] : rv0, fB = hi ? s0[rowB] : rv1;
        float oA = hi ? s1[rowA] : rv2, oB = hi ? s1[rowB] : rv3;
        cA = sigf(fA) * cA + sigf(iA) * tanh_(gA);
        cB = sigf(fB) * cB + sigf(iB) * tanh_(gB);
        float hA = sigf(oA) * tanh_(cA);
        float hB = sigf(oB) * tanh_(cB);
        hnxt[rowA * HH + hh] = hA;
        hnxt[rowB * HH + hh] = hB;
        hout[((size_t)t * BB + b0 + rowA) * HH + hh] = hA;
        hout[((size_t)t * BB + b0 + rowB) * HH + hh] = hB;
        __syncthreads();
    }
}

// ---------------- FC head ----------------------------------------------------
__global__ __launch_bounds__(128) void head_kernel(const float* __restrict__ fc1w,
                                                   const float* __restrict__ fc1b,
                                                   const float* __restrict__ fc2w,
                                                   const float* __restrict__ fc2b,
                                                   float* __restrict__ out) {
    __shared__ float last[128], z[128];
    int b = blockIdx.x, tid = threadIdx.x;
    last[tid] = g_h0[((size_t)(TT - 1) * BB + b) * HH + tid];
    __syncthreads();
    float a = fc1b[tid];
#pragma unroll 4
    for (int k = 0; k < HH; k++) a = fmaf(last[k], fc1w[tid * HH + k], a);
    z[tid] = fmaxf(a, 0.f);
    __syncthreads();
    if (tid < 7) {
        float y = fc2b[tid];
#pragma unroll 4
        for (int k = 0; k < HH; k++) y = fmaf(z[k], fc2w[tid * HH + k], y);
        out[b * 7 + tid] = y;
    }
}

// ---------------- launcher ---------------------------------------------------
extern "C" void kernel_launch(void* const* d_in, const int* in_sizes, int n_in,
                              void* d_out, int out_size) {
    (void)in_sizes; (void)n_in; (void)out_size;
    const float* x    = (const float*)d_in[0];
    const float* wih0 = (const float*)d_in[1];
    const float* whh0 = (const float*)d_in[2];
    const float* bih0 = (const float*)d_in[3];
    const float* bhh0 = (const float*)d_in[4];
    const float* wih1 = (const float*)d_in[5];
    const float* whh1 = (const float*)d_in[6];
    const float* bih1 = (const float*)d_in[7];
    const float* bhh1 = (const float*)d_in[8];
    const float* wih2 = (const float*)d_in[9];
    const float* whh2 = (const float*)d_in[10];
    const float* bih2 = (const float*)d_in[11];
    const float* bhh2 = (const float*)d_in[12];
    const float* fc1w = (const float*)d_in[13];
    const float* fc1b = (const float*)d_in[14];
    const float* fc2w = (const float*)d_in[15];
    const float* fc2b = (const float*)d_in[16];
    float* out = (float*)d_out;

    cudaFuncSetAttribute(rec_kernel, cudaFuncAttributeMaxDynamicSharedMemorySize, 135168);
    cudaFuncSetAttribute(proj_mma_kernel, cudaFuncAttributeMaxDynamicSharedMemorySize, SMW_TOT);

    prep_a_kernel<<<390, 256>>>(whh0, whh1, whh2,
                                bih0, bhh0, bih1, bhh1, bih2, bhh2);  // 1
    prep_b_kernel<<<256, 256>>>(wih1, wih2);                          // 2
    proj0_kernel<<<512, 256>>>(x, wih0);                              // 3
    rec_kernel<<<128, 256, 135168>>>(0, 0);                           // 4 -> g_h0 (ncu target)
    proj_mma_kernel<<<dim3(2048, 4), 256, SMW_TOT>>>(0);              // 5
    rec_kernel<<<128, 256, 135168>>>(1, 1);                           // 6 -> g_h1
    proj_mma_kernel<<<dim3(2048, 4), 256, SMW_TOT>>>(1);              // 7
    rec_kernel<<<128, 256, 135168>>>(2, 0);                           // 8 -> g_h0
    head_kernel<<<512, 128>>>(fc1w, fc1b, fc2w, fc2b, out);           // 9
}

// round 7
// speedup vs baseline: 1.4036x; 1.0976x over previous
#include <cuda_runtime.h>
#include <cuda_bf16.h>
#include <cstdint>

typedef unsigned long long ull;

#define TT 512
#define BB 512
#define HH 128
#define G4 512
#define MTOT 262144              // T*B

// ---------------- device-global scratch (no allocations allowed) ------------
__device__ __align__(16) float g_xg[134217728];    // [m][512] gate preacts (m-major)
__device__ __align__(16) float g_h0[33554432];     // [m][H]
__device__ __align__(16) float g_h1[33554432];     // [m][H]
__device__ __align__(16) ull   g_wj0[3][256 * 64]; // W_hh cols 0..255 (i,f): [j][k2]
__device__ __align__(16) ull   g_wj1[3][32 * 256 * 2]; // W_hh cols 256..511 (g,o): [q][col][2]
__device__ __align__(16) uint32_t g_wmma[2][4][16384]; // W_ih l1,l2: [ntile128][hi|lo] frag-order words
__device__ float g_bias[3][512];                   // b_ih + b_hh

// ---------------- helpers ---------------------------------------------------
__device__ __forceinline__ void fma2(ull& d, ull a, ull b) {
    asm("fma.rn.f32x2 %0, %1, %2, %0;" : "+l"(d) : "l"(a), "l"(b));
}
__device__ __forceinline__ ull pack2(float a, float b) {
    ull r; asm("mov.b64 %0, {%1,%2};" : "=l"(r) : "f"(a), "f"(b)); return r;
}
__device__ __forceinline__ float sum2(ull v) {
    float lo, hi; asm("mov.b64 {%0,%1}, %2;" : "=f"(lo), "=f"(hi) : "l"(v));
    return lo + hi;
}
__device__ __forceinline__ float sigf(float x) {
    return __fdividef(1.f, 1.f + __expf(-x));
}
__device__ __forceinline__ float tanh_(float x) {
    return 1.f - __fdividef(2.f, 1.f + __expf(2.f * x));
}
__device__ __forceinline__ uint32_t packbf(float x, float y) {
    __nv_bfloat162 t = __floats2bfloat162_rn(x, y);
    return *(uint32_t*)&t;
}
__device__ __forceinline__ void mma_bf16(float* d, const uint32_t* a, const uint32_t* b) {
    asm volatile(
        "mma.sync.aligned.m16n8k16.row.col.f32.bf16.bf16.f32 "
        "{%0,%1,%2,%3}, {%4,%5,%6,%7}, {%8,%9}, {%0,%1,%2,%3};"
        : "+f"(d[0]), "+f"(d[1]), "+f"(d[2]), "+f"(d[3])
        : "r"(a[0]), "r"(a[1]), "r"(a[2]), "r"(a[3]), "r"(b[0]), "r"(b[1]));
}

// ---------------- weight prep (3 launches; aligns proj_mma to launch #6) -----
__global__ void prep_a_kernel(const float* __restrict__ whh0, const float* __restrict__ whh1,
                              const float* __restrict__ whh2) {
    int idx = blockIdx.x * 256 + threadIdx.x;
    if (idx < 98304) {
        int l = idx >> 15, r = idx & 32767;
        int k2 = r >> 9, j = r & 511;
        const float* w = (l == 0) ? whh0 : (l == 1) ? whh1 : whh2;
        ull p = pack2(w[j * HH + 2 * k2], w[j * HH + 2 * k2 + 1]);
        if (j < 256) g_wj0[l][j * 64 + k2] = p;
        else         g_wj1[l][((k2 >> 1) * 256 + (j - 256)) * 2 + (k2 & 1)] = p;
    }
}

__global__ void prep_bias_kernel(const float* __restrict__ bih0, const float* __restrict__ bhh0,
                                 const float* __restrict__ bih1, const float* __restrict__ bhh1,
                                 const float* __restrict__ bih2, const float* __restrict__ bhh2) {
    int idx = blockIdx.x * 256 + threadIdx.x;
    if (idx < 1536) {
        int l = idx >> 9, j = idx & 511;
        const float* bi = (l == 0) ? bih0 : (l == 1) ? bih1 : bih2;
        const float* bh = (l == 0) ? bhh0 : (l == 1) ? bhh1 : bhh2;
        g_bias[l][j] = bi[j] + bh[j];
    }
}

// W_ih (l1,l2) -> bf16 hi/lo fragment order
__global__ void prep_b_kernel(const float* __restrict__ wih1, const float* __restrict__ wih2) {
    int idx = blockIdx.x * 256 + threadIdx.x;
    if (idx >= 65536) return;
    int p = idx >> 15, r2 = idx & 32767;
    int j = r2 >> 6, kw = r2 & 63;
    const float* w = p ? wih2 : wih1;
    float2 v = *(const float2*)(w + j * HH + 2 * kw);
    float xh = __bfloat162float(__float2bfloat16(v.x));
    float yh = __bfloat162float(__float2bfloat16(v.y));
    uint32_t wh = packbf(v.x, v.y);
    uint32_t wl = packbf(v.x - xh, v.y - yh);
    int ntile = j >> 7, n = j & 127;
    int ntt = n >> 3, nr = n & 7;
    int kt = kw >> 3, wi = kw & 7, w3 = wi & 3, reg = wi >> 2;
    uint32_t dst = (uint32_t)(((kt * 16 + ntt) * 32 + nr * 4 + w3) * 2 + reg);
    g_wmma[p][ntile][dst] = wh;
    g_wmma[p][ntile][8192 + dst] = wl;
}

// ---------------- layer-0 input projection (K = 8), m-major output -----------
__global__ __launch_bounds__(256) void proj0_kernel(const float* __restrict__ x,
                                                    const float* __restrict__ w0) {
    __shared__ float ws[4096], xs[4096], bs[512];
    int t = blockIdx.x, tid = threadIdx.x;
    for (int i = tid; i < 4096; i += 256) ws[i] = w0[i];
    for (int i = tid; i < 512; i += 256) bs[i] = g_bias[0][i];
    for (int i = tid; i < 4096; i += 256) {
        int b = i >> 3, f = i & 7;
        xs[i] = x[(size_t)b * 4096 + t * 8 + f];   // x[b][t][f]
    }
    __syncthreads();
    int j0 = tid, j1 = tid + 256;
    float w0r[8], w1r[8];
#pragma unroll
    for (int f = 0; f < 8; f++) { w0r[f] = ws[j0 * 8 + f]; w1r[f] = ws[j1 * 8 + f]; }
    float bz0 = bs[j0], bz1 = bs[j1];
    float* outt = g_xg + (size_t)t * BB * G4;
    for (int b = 0; b < BB; b++) {
        float a0 = bz0, a1 = bz1;
#pragma unroll
        for (int f = 0; f < 8; f++) {
            float xv = xs[b * 8 + f];
            a0 = fmaf(xv, w0r[f], a0);
            a1 = fmaf(xv, w1r[f], a1);
        }
        outt[(size_t)b * G4 + j0] = a0;
        outt[(size_t)b * G4 + j1] = a1;
    }
}

// ---------------- layers 1,2 input projection: mma.sync bf16 3-split GEMM ----
// CTA tile 128m x 128n, K=128. 8 warps = 4 m-warps x 2 n-halves; warp 32m x 64n.
#define ALO_W 8192
#define BHI_W 16384
#define BLO_W 24576
#define SMW_TOT (32768 * 4 + 512)

__global__ __launch_bounds__(256, 1) void proj_mma_kernel(int p) {
    extern __shared__ uint32_t smw[];
    float* bias = (float*)(smw + 32768);
    int tid = threadIdx.x;
    int wid = tid >> 5, lane = tid & 31;
    int mw = wid & 3, nh = wid >> 2;
    const float* hin = p ? g_h1 : g_h0;
    int mbase = blockIdx.x * 128;
    int nbase = blockIdx.y * 128;

    // A: load h rows (fp32), split hi/lo bf16 into fragment-order smem
#pragma unroll
    for (int it = 0; it < 32; it++) {
        int idx = it * 256 + tid;
        int m = idx >> 6, kw = idx & 63;
        float2 v = *(const float2*)(hin + (size_t)(mbase + m) * HH + 2 * kw);
        float xh = __bfloat162float(__float2bfloat16(v.x));
        float yh = __bfloat162float(__float2bfloat16(v.y));
        uint32_t whw = packbf(v.x, v.y);
        uint32_t wlw = packbf(v.x - xh, v.y - yh);
        int mt = m >> 4, row = m & 15, half = row >> 3, r = row & 7;
        int kt = kw >> 3, wi = kw & 7, w3 = wi & 3, wh2 = wi >> 2;
        uint32_t dst = (uint32_t)(((mt * 8 + kt) * 32 + r * 4 + w3) * 4 + half + 2 * wh2);
        smw[dst] = whw;
        smw[ALO_W + dst] = wlw;
    }
    // B: straight copy of prepped fragment-order hi+lo (64 KB)
    {
        const uint4* src = (const uint4*)g_wmma[p][blockIdx.y];
        uint4* dst = (uint4*)(smw + BHI_W);
#pragma unroll
        for (int it = 0; it < 16; it++) dst[it * 256 + tid] = src[it * 256 + tid];
    }
    if (tid < 128) bias[tid] = g_bias[p + 1][nbase + tid];
    __syncthreads();

    float acc[2][8][4];
#pragma unroll
    for (int mt = 0; mt < 2; mt++)
#pragma unroll
        for (int nt = 0; nt < 8; nt++)
#pragma unroll
            for (int i = 0; i < 4; i++) acc[mt][nt][i] = 0.f;

#pragma unroll
    for (int kt = 0; kt < 8; kt++) {
        uint4 ah[2], al[2];
#pragma unroll
        for (int mt = 0; mt < 2; mt++) {
            int mtile = mw * 2 + mt;
            ah[mt] = *((const uint4*)smw + ((mtile * 8 + kt) * 32 + lane));
            al[mt] = *((const uint4*)(smw + ALO_W) + ((mtile * 8 + kt) * 32 + lane));
        }
        uint2 bh[8], bl[8];
#pragma unroll
        for (int nt = 0; nt < 8; nt++) {
            int ntt = nh * 8 + nt;
            bh[nt] = *((const uint2*)(smw + BHI_W) + ((kt * 16 + ntt) * 32 + lane));
            bl[nt] = *((const uint2*)(smw + BLO_W) + ((kt * 16 + ntt) * 32 + lane));
        }
#pragma unroll
        for (int mt = 0; mt < 2; mt++)
#pragma unroll
            for (int nt = 0; nt < 8; nt++) {
                mma_bf16(acc[mt][nt], (const uint32_t*)&ah[mt], (const uint32_t*)&bh[nt]);
                mma_bf16(acc[mt][nt], (const uint32_t*)&al[mt], (const uint32_t*)&bh[nt]);
                mma_bf16(acc[mt][nt], (const uint32_t*)&ah[mt], (const uint32_t*)&bl[nt]);
            }
    }

    // epilogue: +bias, m-major float2 stores (quad covers 32B contiguous)
    int r = lane >> 2, cc = lane & 3;
#pragma unroll
    for (int mt = 0; mt < 2; mt++) {
        int m0 = mbase + mw * 32 + mt * 16 + r;
#pragma unroll
        for (int nt = 0; nt < 8; nt++) {
            int nl = nh * 64 + nt * 8 + 2 * cc;
            float b0v = bias[nl], b1v = bias[nl + 1];
            float2 v0 = make_float2(acc[mt][nt][0] + b0v, acc[mt][nt][1] + b1v);
            float2 v1 = make_float2(acc[mt][nt][2] + b0v, acc[mt][nt][3] + b1v);
            *(float2*)(g_xg + (size_t)m0 * G4 + nbase + nl) = v0;
            *(float2*)(g_xg + (size_t)(m0 + 8) * G4 + nbase + nl) = v1;
        }
    }
}

// ---------------- recurrent LSTM layer ---------------------------------------
__global__ __launch_bounds__(256, 1) void rec_kernel(int l, int outsel) {
    extern __shared__ char smraw[];
    ull*   wsm = (ull*)smraw;                     // [32 q][256 col][2]  128 KB
    float* hfb = (float*)(smraw + 131072);        // 2 x [4][128]          4 KB

    int tid = threadIdx.x;
    int lane = tid & 31, wid = tid >> 5;
    int sub = lane & 15, hi = lane >> 4;
    int hh = (wid << 4) + sub;
    int j0 = hh + (hi << 7);
    int j1 = j0 + 256;
    int b0 = blockIdx.x * 4;
    float* hout = outsel ? g_h1 : g_h0;

    {
        const ulonglong2* src = (const ulonglong2*)g_wj1[l];
        ulonglong2* dst = (ulonglong2*)wsm;
        for (int i = tid; i < 8192; i += 256) dst[i] = src[i];
    }
    ull wr[64];
    {
        const ull* src = g_wj0[l] + j0 * 64;
#pragma unroll
        for (int k = 0; k < 64; k++) wr[k] = src[k];
    }
    hfb[tid] = 0.f; hfb[tid + 256] = 0.f;
    float cA = 0.f, cB = 0.f;
    int rowA = hi ? 2 : 0, rowB = hi ? 3 : 1;
    int ra = hi ? 0 : 2;
    __syncthreads();

    for (int t = 0; t < TT; t++) {
        const float* hcur = hfb + ((t & 1) << 9);
        float* hnxt = hfb + (((t + 1) & 1) << 9);
        const float* xrow = g_xg + ((size_t)t * BB + b0) * G4;
        float xa0[4], xa1[4];
#pragma unroll
        for (int r = 0; r < 4; r++) {
            xa0[r] = xrow[r * G4 + j0];
            xa1[r] = xrow[r * G4 + j1];
        }
        ull acc0[4] = {0, 0, 0, 0}, acc1[4] = {0, 0, 0, 0};
#pragma unroll
        for (int q = 0; q < 32; q++) {
            ulonglong2 hv0 = *(const ulonglong2*)(hcur + 0 * HH + 4 * q);
            ulonglong2 hv1 = *(const ulonglong2*)(hcur + 1 * HH + 4 * q);
            ulonglong2 hv2 = *(const ulonglong2*)(hcur + 2 * HH + 4 * q);
            ulonglong2 hv3 = *(const ulonglong2*)(hcur + 3 * HH + 4 * q);
            ulonglong2 wp = *(const ulonglong2*)(wsm + (q * 256 + j0) * 2);
            fma2(acc0[0], hv0.x, wr[2 * q]); fma2(acc0[0], hv0.y, wr[2 * q + 1]);
            fma2(acc0[1], hv1.x, wr[2 * q]); fma2(acc0[1], hv1.y, wr[2 * q + 1]);
            fma2(acc0[2], hv2.x, wr[2 * q]); fma2(acc0[2], hv2.y, wr[2 * q + 1]);
            fma2(acc0[3], hv3.x, wr[2 * q]); fma2(acc0[3], hv3.y, wr[2 * q + 1]);
            fma2(acc1[0], hv0.x, wp.x);      fma2(acc1[0], hv0.y, wp.y);
            fma2(acc1[1], hv1.x, wp.x);      fma2(acc1[1], hv1.y, wp.y);
            fma2(acc1[2], hv2.x, wp.x);      fma2(acc1[2], hv2.y, wp.y);
            fma2(acc1[3], hv3.x, wp.x);      fma2(acc1[3], hv3.y, wp.y);
        }
        float s0[4], s1[4];
#pragma unroll
        for (int r = 0; r < 4; r++) {
            s0[r] = sum2(acc0[r]) + xa0[r];
            s1[r] = sum2(acc1[r]) + xa1[r];
        }
        float rv0 = __shfl_xor_sync(0xFFFFFFFFu, s0[ra],     16);
        float rv1 = __shfl_xor_sync(0xFFFFFFFFu, s0[ra + 1], 16);
        float rv2 = __shfl_xor_sync(0xFFFFFFFFu, s1[ra],     16);
        float rv3 = __shfl_xor_sync(0xFFFFFFFFu, s1[ra + 1], 16);
        float iA = hi ? rv0 : s0[rowA], iB = hi ? rv1 : s0[rowB];
        float gA = hi ? rv2 : s1[rowA], gB = hi ? rv3 : s1[rowB];
        float fA = hi ? s0[rowA] : rv0, fB = hi ? s0[rowB] : rv1;
        float oA = hi ? s1[rowA] : rv2, oB = hi ? s1[rowB] : rv3;
        cA = sigf(fA) * cA + sigf(iA) * tanh_(gA);
        cB = sigf(fB) * cB + sigf(iB) * tanh_(gB);
        float hA = sigf(oA) * tanh_(cA);
        float hB = sigf(oB) * tanh_(cB);
        hnxt[rowA * HH + hh] = hA;
        hnxt[rowB * HH + hh] = hB;
        hout[((size_t)t * BB + b0 + rowA) * HH + hh] = hA;
        hout[((size_t)t * BB + b0 + rowB) * HH + hh] = hB;
        __syncthreads();
    }
}

// ---------------- FC head ----------------------------------------------------
__global__ __launch_bounds__(128) void head_kernel(const float* __restrict__ fc1w,
                                                   const float* __restrict__ fc1b,
                                                   const float* __restrict__ fc2w,
                                                   const float* __restrict__ fc2b,
                                                   float* __restrict__ out) {
    __shared__ float last[128], z[128];
    int b = blockIdx.x, tid = threadIdx.x;
    last[tid] = g_h0[((size_t)(TT - 1) * BB + b) * HH + tid];
    __syncthreads();
    float a = fc1b[tid];
#pragma unroll 4
    for (int k = 0; k < HH; k++) a = fmaf(last[k], fc1w[tid * HH + k], a);
    z[tid] = fmaxf(a, 0.f);
    __syncthreads();
    if (tid < 7) {
        float y = fc2b[tid];
#pragma unroll 4
        for (int k = 0; k < HH; k++) y = fmaf(z[k], fc2w[tid * HH + k], y);
        out[b * 7 + tid] = y;
    }
}

// ---------------- launcher ---------------------------------------------------
extern "C" void kernel_launch(void* const* d_in, const int* in_sizes, int n_in,
                              void* d_out, int out_size) {
    (void)in_sizes; (void)n_in; (void)out_size;
    const float* x    = (const float*)d_in[0];
    const float* wih0 = (const float*)d_in[1];
    const float* whh0 = (const float*)d_in[2];
    const float* bih0 = (const float*)d_in[3];
    const float* bhh0 = (const float*)d_in[4];
    const float* wih1 = (const float*)d_in[5];
    const float* whh1 = (const float*)d_in[6];
    const float* bih1 = (const float*)d_in[7];
    const float* bhh1 = (const float*)d_in[8];
    const float* wih2 = (const float*)d_in[9];
    const float* whh2 = (const float*)d_in[10];
    const float* bih2 = (const float*)d_in[11];
    const float* bhh2 = (const float*)d_in[12];
    const float* fc1w = (const float*)d_in[13];
    const float* fc1b = (const float*)d_in[14];
    const float* fc2w = (const float*)d_in[15];
    const float* fc2b = (const float*)d_in[16];
    float* out = (float*)d_out;

    cudaFuncSetAttribute(rec_kernel, cudaFuncAttributeMaxDynamicSharedMemorySize, 135168);
    cudaFuncSetAttribute(proj_mma_kernel, cudaFuncAttributeMaxDynamicSharedMemorySize, SMW_TOT);

    prep_a_kernel<<<384, 256>>>(whh0, whh1, whh2);                    // 1
    prep_bias_kernel<<<6, 256>>>(bih0, bhh0, bih1, bhh1, bih2, bhh2); // 2
    prep_b_kernel<<<256, 256>>>(wih1, wih2);                          // 3
    proj0_kernel<<<512, 256>>>(x, wih0);                              // 4
    rec_kernel<<<128, 256, 135168>>>(0, 0);                           // 5 -> g_h0
    proj_mma_kernel<<<dim3(2048, 4), 256, SMW_TOT>>>(0);              // 6 (ncu target)
    rec_kernel<<<128, 256, 135168>>>(1, 1);                           // 7 -> g_h1
    proj_mma_kernel<<<dim3(2048, 4), 256, SMW_TOT>>>(1);              // 8
    rec_kernel<<<128, 256, 135168>>>(2, 0);                           // 9 -> g_h0
    head_kernel<<<512, 128>>>(fc1w, fc1b, fc2w, fc2b, out);           // 10
}

// round 8
// speedup vs baseline: 1.5925x; 1.1346x over previous
#include <cuda_runtime.h>
#include <cuda_bf16.h>
#include <cstdint>

typedef unsigned long long ull;

#define TT 512
#define BB 512
#define HH 128
#define G4 512
#define MTOT 262144              // T*B

// ---------------- device-global scratch (no allocations allowed) ------------
__device__ __align__(16) float g_xg[134217728];    // [m][512] gate preacts (m-major)
__device__ __align__(16) float g_h0[33554432];     // [m][H]
__device__ __align__(16) float g_h1[33554432];     // [m][H]
__device__ __align__(16) uint32_t g_wfh[3][32768]; // W_hh hi bf16 A-frags [mt32][kt8][lane32][reg4]
__device__ __align__(16) uint32_t g_wfl[3][32768]; // W_hh lo bf16 A-frags (same layout)
__device__ __align__(16) uint32_t g_wmma[2][4][16384]; // W_ih l1,l2: [ntile128][hi|lo] frag words
__device__ float g_bias[3][512];                   // b_ih + b_hh

// ---------------- helpers ---------------------------------------------------
__device__ __forceinline__ float sigf(float x) {
    return __fdividef(1.f, 1.f + __expf(-x));
}
__device__ __forceinline__ float tanh_(float x) {
    return 1.f - __fdividef(2.f, 1.f + __expf(2.f * x));
}
__device__ __forceinline__ uint32_t packbf(float x, float y) {
    __nv_bfloat162 t = __floats2bfloat162_rn(x, y);
    return *(uint32_t*)&t;
}
__device__ __forceinline__ void mma_bf16(float* d, const uint32_t* a, const uint32_t* b) {
    asm volatile(
        "mma.sync.aligned.m16n8k16.row.col.f32.bf16.bf16.f32 "
        "{%0,%1,%2,%3}, {%4,%5,%6,%7}, {%8,%9}, {%0,%1,%2,%3};"
        : "+f"(d[0]), "+f"(d[1]), "+f"(d[2]), "+f"(d[3])
        : "r"(a[0]), "r"(a[1]), "r"(a[2]), "r"(a[3]), "r"(b[0]), "r"(b[1]));
}

// ---------------- prep: W_hh -> bf16 hi/lo A-fragment order ------------------
// A frag m16k16 row-major: reg j -> row = (lane>>2) + 8*(j&1), word = (lane&3) + 4*(j>>1)
__global__ void prep_wfrag_kernel(const float* __restrict__ whh0, const float* __restrict__ whh1,
                                  const float* __restrict__ whh2) {
    int idx = blockIdx.x * 256 + threadIdx.x;
    if (idx >= 98304) return;
    int l = idx >> 15, r = idx & 32767;
    int reg = r & 3, lane = (r >> 2) & 31, kt = (r >> 7) & 7, mt = r >> 10;
    const float* w = (l == 0) ? whh0 : (l == 1) ? whh1 : whh2;
    int g = mt * 16 + (lane >> 2) + 8 * (reg & 1);
    int wrd = (lane & 3) + 4 * (reg >> 1);
    int k = kt * 16 + 2 * wrd;
    float v0 = w[g * HH + k], v1 = w[g * HH + k + 1];
    float h0 = __bfloat162float(__float2bfloat16(v0));
    float h1 = __bfloat162float(__float2bfloat16(v1));
    g_wfh[l][r] = packbf(v0, v1);
    g_wfl[l][r] = packbf(v0 - h0, v1 - h1);
}

__global__ void prep_bias_kernel(const float* __restrict__ bih0, const float* __restrict__ bhh0,
                                 const float* __restrict__ bih1, const float* __restrict__ bhh1,
                                 const float* __restrict__ bih2, const float* __restrict__ bhh2) {
    int idx = blockIdx.x * 256 + threadIdx.x;
    if (idx < 1536) {
        int l = idx >> 9, j = idx & 511;
        const float* bi = (l == 0) ? bih0 : (l == 1) ? bih1 : bih2;
        const float* bh = (l == 0) ? bhh0 : (l == 1) ? bhh1 : bhh2;
        g_bias[l][j] = bi[j] + bh[j];
    }
}

// W_ih (l1,l2) -> bf16 hi/lo B-fragment order (for proj_mma)
__global__ void prep_b_kernel(const float* __restrict__ wih1, const float* __restrict__ wih2) {
    int idx = blockIdx.x * 256 + threadIdx.x;
    if (idx >= 65536) return;
    int p = idx >> 15, r2 = idx & 32767;
    int j = r2 >> 6, kw = r2 & 63;
    const float* w = p ? wih2 : wih1;
    float2 v = *(const float2*)(w + j * HH + 2 * kw);
    float xh = __bfloat162float(__float2bfloat16(v.x));
    float yh = __bfloat162float(__float2bfloat16(v.y));
    uint32_t wh = packbf(v.x, v.y);
    uint32_t wl = packbf(v.x - xh, v.y - yh);
    int ntile = j >> 7, n = j & 127;
    int ntt = n >> 3, nr = n & 7;
    int kt = kw >> 3, wi = kw & 7, w3 = wi & 3, reg = wi >> 2;
    uint32_t dst = (uint32_t)(((kt * 16 + ntt) * 32 + nr * 4 + w3) * 2 + reg);
    g_wmma[p][ntile][dst] = wh;
    g_wmma[p][ntile][8192 + dst] = wl;
}

// ---------------- layer-0 input projection (K = 8), m-major output -----------
__global__ __launch_bounds__(256) void proj0_kernel(const float* __restrict__ x,
                                                    const float* __restrict__ w0) {
    __shared__ float ws[4096], xs[4096], bs[512];
    int t = blockIdx.x, tid = threadIdx.x;
    for (int i = tid; i < 4096; i += 256) ws[i] = w0[i];
    for (int i = tid; i < 512; i += 256) bs[i] = g_bias[0][i];
    for (int i = tid; i < 4096; i += 256) {
        int b = i >> 3, f = i & 7;
        xs[i] = x[(size_t)b * 4096 + t * 8 + f];
    }
    __syncthreads();
    int j0 = tid, j1 = tid + 256;
    float w0r[8], w1r[8];
#pragma unroll
    for (int f = 0; f < 8; f++) { w0r[f] = ws[j0 * 8 + f]; w1r[f] = ws[j1 * 8 + f]; }
    float bz0 = bs[j0], bz1 = bs[j1];
    float* outt = g_xg + (size_t)t * BB * G4;
    for (int b = 0; b < BB; b++) {
        float a0 = bz0, a1 = bz1;
#pragma unroll
        for (int f = 0; f < 8; f++) {
            float xv = xs[b * 8 + f];
            a0 = fmaf(xv, w0r[f], a0);
            a1 = fmaf(xv, w1r[f], a1);
        }
        outt[(size_t)b * G4 + j0] = a0;
        outt[(size_t)b * G4 + j1] = a1;
    }
}

// ---------------- layers 1,2 input projection: mma.sync bf16 3-split GEMM ----
#define ALO_W 8192
#define BHI_W 16384
#define BLO_W 24576
#define SMW_TOT (32768 * 4 + 512)

__global__ __launch_bounds__(256, 1) void proj_mma_kernel(int p) {
    extern __shared__ uint32_t smw[];
    float* bias = (float*)(smw + 32768);
    int tid = threadIdx.x;
    int wid = tid >> 5, lane = tid & 31;
    int mw = wid & 3, nh = wid >> 2;
    const float* hin = p ? g_h1 : g_h0;
    int mbase = blockIdx.x * 128;
    int nbase = blockIdx.y * 128;

#pragma unroll
    for (int it = 0; it < 32; it++) {
        int idx = it * 256 + tid;
        int m = idx >> 6, kw = idx & 63;
        float2 v = *(const float2*)(hin + (size_t)(mbase + m) * HH + 2 * kw);
        float xh = __bfloat162float(__float2bfloat16(v.x));
        float yh = __bfloat162float(__float2bfloat16(v.y));
        uint32_t whw = packbf(v.x, v.y);
        uint32_t wlw = packbf(v.x - xh, v.y - yh);
        int mt = m >> 4, row = m & 15, half = row >> 3, r = row & 7;
        int kt = kw >> 3, wi = kw & 7, w3 = wi & 3, wh2 = wi >> 2;
        uint32_t dst = (uint32_t)(((mt * 8 + kt) * 32 + r * 4 + w3) * 4 + half + 2 * wh2);
        smw[dst] = whw;
        smw[ALO_W + dst] = wlw;
    }
    {
        const uint4* src = (const uint4*)g_wmma[p][blockIdx.y];
        uint4* dst = (uint4*)(smw + BHI_W);
#pragma unroll
        for (int it = 0; it < 16; it++) dst[it * 256 + tid] = src[it * 256 + tid];
    }
    if (tid < 128) bias[tid] = g_bias[p + 1][nbase + tid];
    __syncthreads();

    float acc[2][8][4];
#pragma unroll
    for (int mt = 0; mt < 2; mt++)
#pragma unroll
        for (int nt = 0; nt < 8; nt++)
#pragma unroll
            for (int i = 0; i < 4; i++) acc[mt][nt][i] = 0.f;

#pragma unroll
    for (int kt = 0; kt < 8; kt++) {
        uint4 ah[2], al[2];
#pragma unroll
        for (int mt = 0; mt < 2; mt++) {
            int mtile = mw * 2 + mt;
            ah[mt] = *((const uint4*)smw + ((mtile * 8 + kt) * 32 + lane));
            al[mt] = *((const uint4*)(smw + ALO_W) + ((mtile * 8 + kt) * 32 + lane));
        }
        uint2 bh[8], bl[8];
#pragma unroll
        for (int nt = 0; nt < 8; nt++) {
            int ntt = nh * 8 + nt;
            bh[nt] = *((const uint2*)(smw + BHI_W) + ((kt * 16 + ntt) * 32 + lane));
            bl[nt] = *((const uint2*)(smw + BLO_W) + ((kt * 16 + ntt) * 32 + lane));
        }
#pragma unroll
        for (int mt = 0; mt < 2; mt++)
#pragma unroll
            for (int nt = 0; nt < 8; nt++) {
                mma_bf16(acc[mt][nt], (const uint32_t*)&ah[mt], (const uint32_t*)&bh[nt]);
                mma_bf16(acc[mt][nt], (const uint32_t*)&al[mt], (const uint32_t*)&bh[nt]);
                mma_bf16(acc[mt][nt], (const uint32_t*)&ah[mt], (const uint32_t*)&bl[nt]);
            }
    }

    int r = lane >> 2, cc = lane & 3;
#pragma unroll
    for (int mt = 0; mt < 2; mt++) {
        int m0 = mbase + mw * 32 + mt * 16 + r;
#pragma unroll
        for (int nt = 0; nt < 8; nt++) {
            int nl = nh * 64 + nt * 8 + 2 * cc;
            float b0v = bias[nl], b1v = bias[nl + 1];
            float2 v0 = make_float2(acc[mt][nt][0] + b0v, acc[mt][nt][1] + b1v);
            float2 v1 = make_float2(acc[mt][nt][2] + b0v, acc[mt][nt][3] + b1v);
            *(float2*)(g_xg + (size_t)m0 * G4 + nbase + nl) = v0;
            *(float2*)(g_xg + (size_t)(m0 + 8) * G4 + nbase + nl) = v1;
        }
    }
}

// ---------------- recurrent LSTM layer on tensor cores -----------------------
// 128 CTAs x 512 thr (16 warps). CTA owns 4 batch rows (n8 tile, cols 0-3 used).
// D[512 gates, 8] = Whh[512,128] x h[128,8]; warp wv owns gates [32wv,32wv+32).
// A-hi frags in regs (64), A-lo frags in smem (128KB), B = h hi/lo frags in smem,
// rebuilt by the epilogue each step. 3-split: Ahi*Bhi + Alo*Bhi + Ahi*Blo.
#define RSM_BSM 131072           // [split2][kt8][lane32][reg2] u32 = 4KB
#define RSM_GSM 135168           // [4 b][512 g] f32 = 8KB
#define RSM_TOT 143360

__global__ __launch_bounds__(512, 1) void rec2_kernel(int l, int outsel) {
    extern __shared__ char sm[];
    uint32_t* bsm = (uint32_t*)(sm + RSM_BSM);
    float* gsm = (float*)(sm + RSM_GSM);
    int tid = threadIdx.x, lane = tid & 31, wv = tid >> 5;
    int b0 = blockIdx.x * 4;
    float* hout = outsel ? g_h1 : g_h0;

    {   // A-lo frags -> smem (layout identical to global)
        const uint4* s = (const uint4*)g_wfl[l];
        uint4* d = (uint4*)sm;
        for (int i = tid; i < 8192; i += 512) d[i] = s[i];
    }
    uint4 ahi[2][8];
#pragma unroll
    for (int mt = 0; mt < 2; mt++)
#pragma unroll
        for (int kt = 0; kt < 8; kt++)
            ahi[mt][kt] = *((const uint4*)g_wfh[l] + (((wv * 2 + mt) * 8 + kt) * 32 + lane));
    for (int i = tid; i < 1024; i += 512) bsm[i] = 0;   // h0 = 0 (and dead lanes)

    int r = lane >> 2, cc = lane & 3;
    int g0 = wv * 32 + r, g1 = g0 + 16;
    // epilogue identity: this thread finalizes (hh, b)
    int eb = tid >> 7, ehh = tid & 127;
    int ekt = ehh >> 4, ew = (ehh & 15) >> 1, ehalf = ehh & 1;
    uint32_t eoff = (uint32_t)(((ekt * 32 + (eb * 4 + (ew & 3))) * 2 + (ew >> 2)) * 4 + ehalf * 2);
    float cst = 0.f;
    __syncthreads();

    for (int t = 0; t < TT; t++) {
        // prefetch xg for this thread's valid acc slots
        float xv[8];
        if (cc < 2) {
            const float* xrow = g_xg + ((size_t)t * BB + b0) * G4;
            int b = 2 * cc;
            xv[0] = xrow[b * G4 + g0];       xv[1] = xrow[(b + 1) * G4 + g0];
            xv[2] = xrow[b * G4 + g0 + 8];   xv[3] = xrow[(b + 1) * G4 + g0 + 8];
            xv[4] = xrow[b * G4 + g1];       xv[5] = xrow[(b + 1) * G4 + g1];
            xv[6] = xrow[b * G4 + g1 + 8];   xv[7] = xrow[(b + 1) * G4 + g1 + 8];
        }
        float acc[2][4];
#pragma unroll
        for (int mt = 0; mt < 2; mt++)
#pragma unroll
            for (int i = 0; i < 4; i++) acc[mt][i] = 0.f;
#pragma unroll
        for (int kt = 0; kt < 8; kt++) {
            uint2 bh = *(const uint2*)&bsm[kt * 64 + lane * 2];
            uint2 bl = *(const uint2*)&bsm[512 + kt * 64 + lane * 2];
#pragma unroll
            for (int mt = 0; mt < 2; mt++) {
                uint4 alo = *((const uint4*)sm + (((wv * 2 + mt) * 8 + kt) * 32 + lane));
                mma_bf16(acc[mt], (const uint32_t*)&ahi[mt][kt], (const uint32_t*)&bh);
                mma_bf16(acc[mt], (const uint32_t*)&alo, (const uint32_t*)&bh);
                mma_bf16(acc[mt], (const uint32_t*)&ahi[mt][kt], (const uint32_t*)&bl);
            }
        }
        if (cc < 2) {
            int b = 2 * cc;
            gsm[b * 512 + g0]           = acc[0][0] + xv[0];
            gsm[(b + 1) * 512 + g0]     = acc[0][1] + xv[1];
            gsm[b * 512 + g0 + 8]       = acc[0][2] + xv[2];
            gsm[(b + 1) * 512 + g0 + 8] = acc[0][3] + xv[3];
            gsm[b * 512 + g1]           = acc[1][0] + xv[4];
            gsm[(b + 1) * 512 + g1]     = acc[1][1] + xv[5];
            gsm[b * 512 + g1 + 8]       = acc[1][2] + xv[6];
            gsm[(b + 1) * 512 + g1 + 8] = acc[1][3] + xv[7];
        }
        __syncthreads();
        {
            const float* gb = gsm + eb * 512;
            float iv = gb[ehh], fv = gb[128 + ehh], gg = gb[256 + ehh], ov = gb[384 + ehh];
            cst = sigf(fv) * cst + sigf(iv) * tanh_(gg);
            float h = sigf(ov) * tanh_(cst);
            hout[((size_t)t * BB + b0 + eb) * HH + ehh] = h;
            __nv_bfloat16 hbh = __float2bfloat16(h);
            __nv_bfloat16 hbl = __float2bfloat16(h - __bfloat162float(hbh));
            *(__nv_bfloat16*)(sm + RSM_BSM + eoff) = hbh;
            *(__nv_bfloat16*)(sm + RSM_BSM + 2048 + eoff) = hbl;
        }
        __syncthreads();
    }
}

// ---------------- FC head ----------------------------------------------------
__global__ __launch_bounds__(128) void head_kernel(const float* __restrict__ fc1w,
                                                   const float* __restrict__ fc1b,
                                                   const float* __restrict__ fc2w,
                                                   const float* __restrict__ fc2b,
                                                   float* __restrict__ out) {
    __shared__ float last[128], z[128];
    int b = blockIdx.x, tid = threadIdx.x;
    last[tid] = g_h0[((size_t)(TT - 1) * BB + b) * HH + tid];
    __syncthreads();
    float a = fc1b[tid];
#pragma unroll 4
    for (int k = 0; k < HH; k++) a = fmaf(last[k], fc1w[tid * HH + k], a);
    z[tid] = fmaxf(a, 0.f);
    __syncthreads();
    if (tid < 7) {
        float y = fc2b[tid];
#pragma unroll 4
        for (int k = 0; k < HH; k++) y = fmaf(z[k], fc2w[tid * HH + k], y);
        out[b * 7 + tid] = y;
    }
}

// ---------------- launcher ---------------------------------------------------
extern "C" void kernel_launch(void* const* d_in, const int* in_sizes, int n_in,
                              void* d_out, int out_size) {
    (void)in_sizes; (void)n_in; (void)out_size;
    const float* x    = (const float*)d_in[0];
    const float* wih0 = (const float*)d_in[1];
    const float* whh0 = (const float*)d_in[2];
    const float* bih0 = (const float*)d_in[3];
    const float* bhh0 = (const float*)d_in[4];
    const float* wih1 = (const float*)d_in[5];
    const float* whh1 = (const float*)d_in[6];
    const float* bih1 = (const float*)d_in[7];
    const float* bhh1 = (const float*)d_in[8];
    const float* wih2 = (const float*)d_in[9];
    const float* whh2 = (const float*)d_in[10];
    const float* bih2 = (const float*)d_in[11];
    const float* bhh2 = (const float*)d_in[12];
    const float* fc1w = (const float*)d_in[13];
    const float* fc1b = (const float*)d_in[14];
    const float* fc2w = (const float*)d_in[15];
    const float* fc2b = (const float*)d_in[16];
    float* out = (float*)d_out;

    cudaFuncSetAttribute(rec2_kernel, cudaFuncAttributeMaxDynamicSharedMemorySize, RSM_TOT);
    cudaFuncSetAttribute(proj_mma_kernel, cudaFuncAttributeMaxDynamicSharedMemorySize, SMW_TOT);

    prep_wfrag_kernel<<<384, 256>>>(whh0, whh1, whh2);                // 1
    prep_bias_kernel<<<6, 256>>>(bih0, bhh0, bih1, bhh1, bih2, bhh2); // 2
    proj0_kernel<<<512, 256>>>(x, wih0);                              // 3
    rec2_kernel<<<128, 512, RSM_TOT>>>(0, 0);                         // 4 -> g_h0 (ncu target)
    prep_b_kernel<<<256, 256>>>(wih1, wih2);                          // 5
    proj_mma_kernel<<<dim3(2048, 4), 256, SMW_TOT>>>(0);              // 6
    rec2_kernel<<<128, 512, RSM_TOT>>>(1, 1);                         // 7 -> g_h1
    proj_mma_kernel<<<dim3(2048, 4), 256, SMW_TOT>>>(1);              // 8
    rec2_kernel<<<128, 512, RSM_TOT>>>(2, 0);                         // 9 -> g_h0
    head_kernel<<<512, 128>>>(fc1w, fc1b, fc2w, fc2b, out);           // 10
}

// round 9
// speedup vs baseline: 1.9599x; 1.2307x over previous
#include <cuda_runtime.h>
#include <cuda_bf16.h>
#include <cstdint>

typedef unsigned long long ull;

#define TT 512
#define BB 512
#define HH 128
#define G4 512
#define MTOT 262144              // T*B

// ---------------- device-global scratch (no allocations allowed) ------------
__device__ __align__(16) float g_xg[134217728];    // [m][512] gate preacts (m-major)
__device__ __align__(16) float g_h0[33554432];     // [m][H]
__device__ __align__(16) float g_h1[33554432];     // [m][H]
__device__ __align__(16) uint32_t g_wfh[3][32768]; // W_hh hi bf16 A-frags [mt32][kt8][lane32][reg4]
__device__ __align__(16) uint32_t g_wfl[3][32768]; // W_hh lo bf16 A-frags (same layout)
__device__ __align__(16) uint32_t g_wmma[2][4][16384]; // W_ih l1,l2: [ntile128][hi|lo] frag words
__device__ float g_bias[3][512];                   // b_ih + b_hh

// ---------------- helpers ---------------------------------------------------
__device__ __forceinline__ float sigf(float x) {
    return __fdividef(1.f, 1.f + __expf(-x));
}
__device__ __forceinline__ float tanh_(float x) {
    return 1.f - __fdividef(2.f, 1.f + __expf(2.f * x));
}
__device__ __forceinline__ uint32_t packbf(float x, float y) {
    __nv_bfloat162 t = __floats2bfloat162_rn(x, y);
    return *(uint32_t*)&t;
}
__device__ __forceinline__ void mma_bf16(float* d, const uint32_t* a, const uint32_t* b) {
    asm volatile(
        "mma.sync.aligned.m16n8k16.row.col.f32.bf16.bf16.f32 "
        "{%0,%1,%2,%3}, {%4,%5,%6,%7}, {%8,%9}, {%0,%1,%2,%3};"
        : "+f"(d[0]), "+f"(d[1]), "+f"(d[2]), "+f"(d[3])
        : "r"(a[0]), "r"(a[1]), "r"(a[2]), "r"(a[3]), "r"(b[0]), "r"(b[1]));
}

// ---------------- prep: W_hh -> bf16 hi/lo A-fragment order ------------------
__global__ void prep_wfrag_kernel(const float* __restrict__ whh0, const float* __restrict__ whh1,
                                  const float* __restrict__ whh2) {
    int idx = blockIdx.x * 256 + threadIdx.x;
    if (idx >= 98304) return;
    int l = idx >> 15, r = idx & 32767;
    int reg = r & 3, lane = (r >> 2) & 31, kt = (r >> 7) & 7, mt = r >> 10;
    const float* w = (l == 0) ? whh0 : (l == 1) ? whh1 : whh2;
    int g = mt * 16 + (lane >> 2) + 8 * (reg & 1);
    int wrd = (lane & 3) + 4 * (reg >> 1);
    int k = kt * 16 + 2 * wrd;
    float v0 = w[g * HH + k], v1 = w[g * HH + k + 1];
    float h0 = __bfloat162float(__float2bfloat16(v0));
    float h1 = __bfloat162float(__float2bfloat16(v1));
    g_wfh[l][r] = packbf(v0, v1);
    g_wfl[l][r] = packbf(v0 - h0, v1 - h1);
}

__global__ void prep_bias_kernel(const float* __restrict__ bih0, const float* __restrict__ bhh0,
                                 const float* __restrict__ bih1, const float* __restrict__ bhh1,
                                 const float* __restrict__ bih2, const float* __restrict__ bhh2) {
    int idx = blockIdx.x * 256 + threadIdx.x;
    if (idx < 1536) {
        int l = idx >> 9, j = idx & 511;
        const float* bi = (l == 0) ? bih0 : (l == 1) ? bih1 : bih2;
        const float* bh = (l == 0) ? bhh0 : (l == 1) ? bhh1 : bhh2;
        g_bias[l][j] = bi[j] + bh[j];
    }
}

// W_ih (l1,l2) -> bf16 hi/lo B-fragment order (for proj_mma)
__global__ void prep_b_kernel(const float* __restrict__ wih1, const float* __restrict__ wih2) {
    int idx = blockIdx.x * 256 + threadIdx.x;
    if (idx >= 65536) return;
    int p = idx >> 15, r2 = idx & 32767;
    int j = r2 >> 6, kw = r2 & 63;
    const float* w = p ? wih2 : wih1;
    float2 v = *(const float2*)(w + j * HH + 2 * kw);
    float xh = __bfloat162float(__float2bfloat16(v.x));
    float yh = __bfloat162float(__float2bfloat16(v.y));
    uint32_t wh = packbf(v.x, v.y);
    uint32_t wl = packbf(v.x - xh, v.y - yh);
    int ntile = j >> 7, n = j & 127;
    int ntt = n >> 3, nr = n & 7;
    int kt = kw >> 3, wi = kw & 7, w3 = wi & 3, reg = wi >> 2;
    uint32_t dst = (uint32_t)(((kt * 16 + ntt) * 32 + nr * 4 + w3) * 2 + reg);
    g_wmma[p][ntile][dst] = wh;
    g_wmma[p][ntile][8192 + dst] = wl;
}

// ---------------- layer-0 input projection (K = 8), m-major output -----------
__global__ __launch_bounds__(256) void proj0_kernel(const float* __restrict__ x,
                                                    const float* __restrict__ w0) {
    __shared__ float ws[4096], xs[4096], bs[512];
    int t = blockIdx.x, tid = threadIdx.x;
    for (int i = tid; i < 4096; i += 256) ws[i] = w0[i];
    for (int i = tid; i < 512; i += 256) bs[i] = g_bias[0][i];
    for (int i = tid; i < 4096; i += 256) {
        int b = i >> 3, f = i & 7;
        xs[i] = x[(size_t)b * 4096 + t * 8 + f];
    }
    __syncthreads();
    int j0 = tid, j1 = tid + 256;
    float w0r[8], w1r[8];
#pragma unroll
    for (int f = 0; f < 8; f++) { w0r[f] = ws[j0 * 8 + f]; w1r[f] = ws[j1 * 8 + f]; }
    float bz0 = bs[j0], bz1 = bs[j1];
    float* outt = g_xg + (size_t)t * BB * G4;
    for (int b = 0; b < BB; b++) {
        float a0 = bz0, a1 = bz1;
#pragma unroll
        for (int f = 0; f < 8; f++) {
            float xv = xs[b * 8 + f];
            a0 = fmaf(xv, w0r[f], a0);
            a1 = fmaf(xv, w1r[f], a1);
        }
        outt[(size_t)b * G4 + j0] = a0;
        outt[(size_t)b * G4 + j1] = a1;
    }
}

// ---------------- layers 1,2 input projection: mma.sync bf16 3-split GEMM ----
#define ALO_W 8192
#define BHI_W 16384
#define BLO_W 24576
#define SMW_TOT (32768 * 4 + 512)

__global__ __launch_bounds__(256, 1) void proj_mma_kernel(int p) {
    extern __shared__ uint32_t smw[];
    float* bias = (float*)(smw + 32768);
    int tid = threadIdx.x;
    int wid = tid >> 5, lane = tid & 31;
    int mw = wid & 3, nh = wid >> 2;
    const float* hin = p ? g_h1 : g_h0;
    int mbase = blockIdx.x * 128;
    int nbase = blockIdx.y * 128;

#pragma unroll
    for (int it = 0; it < 32; it++) {
        int idx = it * 256 + tid;
        int m = idx >> 6, kw = idx & 63;
        float2 v = *(const float2*)(hin + (size_t)(mbase + m) * HH + 2 * kw);
        float xh = __bfloat162float(__float2bfloat16(v.x));
        float yh = __bfloat162float(__float2bfloat16(v.y));
        uint32_t whw = packbf(v.x, v.y);
        uint32_t wlw = packbf(v.x - xh, v.y - yh);
        int mt = m >> 4, row = m & 15, half = row >> 3, r = row & 7;
        int kt = kw >> 3, wi = kw & 7, w3 = wi & 3, wh2 = wi >> 2;
        uint32_t dst = (uint32_t)(((mt * 8 + kt) * 32 + r * 4 + w3) * 4 + half + 2 * wh2);
        smw[dst] = whw;
        smw[ALO_W + dst] = wlw;
    }
    {
        const uint4* src = (const uint4*)g_wmma[p][blockIdx.y];
        uint4* dst = (uint4*)(smw + BHI_W);
#pragma unroll
        for (int it = 0; it < 16; it++) dst[it * 256 + tid] = src[it * 256 + tid];
    }
    if (tid < 128) bias[tid] = g_bias[p + 1][nbase + tid];
    __syncthreads();

    float acc[2][8][4];
#pragma unroll
    for (int mt = 0; mt < 2; mt++)
#pragma unroll
        for (int nt = 0; nt < 8; nt++)
#pragma unroll
            for (int i = 0; i < 4; i++) acc[mt][nt][i] = 0.f;

#pragma unroll
    for (int kt = 0; kt < 8; kt++) {
        uint4 ah[2], al[2];
#pragma unroll
        for (int mt = 0; mt < 2; mt++) {
            int mtile = mw * 2 + mt;
            ah[mt] = *((const uint4*)smw + ((mtile * 8 + kt) * 32 + lane));
            al[mt] = *((const uint4*)(smw + ALO_W) + ((mtile * 8 + kt) * 32 + lane));
        }
        uint2 bh[8], bl[8];
#pragma unroll
        for (int nt = 0; nt < 8; nt++) {
            int ntt = nh * 8 + nt;
            bh[nt] = *((const uint2*)(smw + BHI_W) + ((kt * 16 + ntt) * 32 + lane));
            bl[nt] = *((const uint2*)(smw + BLO_W) + ((kt * 16 + ntt) * 32 + lane));
        }
#pragma unroll
        for (int mt = 0; mt < 2; mt++)
#pragma unroll
            for (int nt = 0; nt < 8; nt++) {
                mma_bf16(acc[mt][nt], (const uint32_t*)&ah[mt], (const uint32_t*)&bh[nt]);
                mma_bf16(acc[mt][nt], (const uint32_t*)&al[mt], (const uint32_t*)&bh[nt]);
                mma_bf16(acc[mt][nt], (const uint32_t*)&ah[mt], (const uint32_t*)&bl[nt]);
            }
    }

    int r = lane >> 2, cc = lane & 3;
#pragma unroll
    for (int mt = 0; mt < 2; mt++) {
        int m0 = mbase + mw * 32 + mt * 16 + r;
#pragma unroll
        for (int nt = 0; nt < 8; nt++) {
            int nl = nh * 64 + nt * 8 + 2 * cc;
            float b0v = bias[nl], b1v = bias[nl + 1];
            float2 v0 = make_float2(acc[mt][nt][0] + b0v, acc[mt][nt][1] + b1v);
            float2 v1 = make_float2(acc[mt][nt][2] + b0v, acc[mt][nt][3] + b1v);
            *(float2*)(g_xg + (size_t)m0 * G4 + nbase + nl) = v0;
            *(float2*)(g_xg + (size_t)(m0 + 8) * G4 + nbase + nl) = v1;
        }
    }
}

// ---------------- recurrent LSTM layer on tensor cores -----------------------
// 128 CTAs x 512 thr (16 warps). CTA owns 4 batch rows.
// N=8 cols of the n8 tile: cols 0-3 = h_hi (batch 0-3), cols 4-7 = h_lo.
// Ahi x B + Alo x B gives the full 4-term split; col c and c+4 summed via
// shfl_xor(2). 32 mma/warp/step (was 48), zero wasted MACs.
#define RSM_BSM 131072           // B frags: [kt8][lane32][reg2] u32 = 2KB
#define RSM_GSM 133120           // [4 b][512 g] f32 = 8KB
#define RSM_TOT 141312

__global__ __launch_bounds__(512, 1) void rec2_kernel(int l, int outsel) {
    extern __shared__ char sm[];
    uint32_t* bsm = (uint32_t*)(sm + RSM_BSM);
    float* gsm = (float*)(sm + RSM_GSM);
    int tid = threadIdx.x, lane = tid & 31, wv = tid >> 5;
    int b0 = blockIdx.x * 4;
    float* hout = outsel ? g_h1 : g_h0;

    {   // A-lo frags -> smem (layout identical to global)
        const uint4* s = (const uint4*)g_wfl[l];
        uint4* d = (uint4*)sm;
        for (int i = tid; i < 8192; i += 512) d[i] = s[i];
    }
    uint4 ahi[2][8];
#pragma unroll
    for (int mt = 0; mt < 2; mt++)
#pragma unroll
        for (int kt = 0; kt < 8; kt++)
            ahi[mt][kt] = *((const uint4*)g_wfh[l] + (((wv * 2 + mt) * 8 + kt) * 32 + lane));
    if (tid < 512) bsm[tid] = 0;   // h0 = 0 (hi and lo halves)

    int r = lane >> 2, cc = lane & 3;
    int g0 = wv * 32 + r, g1 = g0 + 16;
    // epilogue identity: this thread finalizes (hh, b)
    int eb = tid >> 7, ehh = tid & 127;
    int ekt = ehh >> 4, ew = (ehh & 15) >> 1, ehalf = ehh & 1;
    uint32_t eoff = (uint32_t)(((ekt * 32 + (eb * 4 + (ew & 3))) * 2 + (ew >> 2)) * 4 + ehalf * 2);
    float cst = 0.f;
    __syncthreads();

    for (int t = 0; t < TT; t++) {
        // prefetch xg for this thread's valid acc slots
        float xv[8];
        if (cc < 2) {
            const float* xrow = g_xg + ((size_t)t * BB + b0) * G4;
            int b = 2 * cc;
            xv[0] = xrow[b * G4 + g0];       xv[1] = xrow[(b + 1) * G4 + g0];
            xv[2] = xrow[b * G4 + g0 + 8];   xv[3] = xrow[(b + 1) * G4 + g0 + 8];
            xv[4] = xrow[b * G4 + g1];       xv[5] = xrow[(b + 1) * G4 + g1];
            xv[6] = xrow[b * G4 + g1 + 8];   xv[7] = xrow[(b + 1) * G4 + g1 + 8];
        }
        float acc[2][4];
#pragma unroll
        for (int mt = 0; mt < 2; mt++)
#pragma unroll
            for (int i = 0; i < 4; i++) acc[mt][i] = 0.f;
#pragma unroll
        for (int kt = 0; kt < 8; kt++) {
            uint2 bh = *(const uint2*)&bsm[kt * 64 + lane * 2];
#pragma unroll
            for (int mt = 0; mt < 2; mt++) {
                uint4 alo = *((const uint4*)sm + (((wv * 2 + mt) * 8 + kt) * 32 + lane));
                mma_bf16(acc[mt], (const uint32_t*)&ahi[mt][kt], (const uint32_t*)&bh);
                mma_bf16(acc[mt], (const uint32_t*)&alo, (const uint32_t*)&bh);
            }
        }
        // combine hi-cols (0-3) with lo-cols (4-7): quad-lane XOR 2
#pragma unroll
        for (int mt = 0; mt < 2; mt++)
#pragma unroll
            for (int i = 0; i < 4; i++)
                acc[mt][i] += __shfl_xor_sync(0xFFFFFFFFu, acc[mt][i], 2);
        if (cc < 2) {
            int b = 2 * cc;
            gsm[b * 512 + g0]           = acc[0][0] + xv[0];
            gsm[(b + 1) * 512 + g0]     = acc[0][1] + xv[1];
            gsm[b * 512 + g0 + 8]       = acc[0][2] + xv[2];
            gsm[(b + 1) * 512 + g0 + 8] = acc[0][3] + xv[3];
            gsm[b * 512 + g1]           = acc[1][0] + xv[4];
            gsm[(b + 1) * 512 + g1]     = acc[1][1] + xv[5];
            gsm[b * 512 + g1 + 8]       = acc[1][2] + xv[6];
            gsm[(b + 1) * 512 + g1 + 8] = acc[1][3] + xv[7];
        }
        __syncthreads();
        {
            const float* gb = gsm + eb * 512;
            float iv = gb[ehh], fv = gb[128 + ehh], gg = gb[256 + ehh], ov = gb[384 + ehh];
            cst = sigf(fv) * cst + sigf(iv) * tanh_(gg);
            float h = sigf(ov) * tanh_(cst);
            hout[((size_t)t * BB + b0 + eb) * HH + ehh] = h;
            __nv_bfloat16 hbh = __float2bfloat16(h);
            __nv_bfloat16 hbl = __float2bfloat16(h - __bfloat162float(hbh));
            *(__nv_bfloat16*)(sm + RSM_BSM + eoff) = hbh;         // n = eb   (hi)
            *(__nv_bfloat16*)(sm + RSM_BSM + eoff + 128) = hbl;   // n = eb+4 (lo), +16 lanes
        }
        __syncthreads();
    }
}

// ---------------- FC head ----------------------------------------------------
__global__ __launch_bounds__(128) void head_kernel(const float* __restrict__ fc1w,
                                                   const float* __restrict__ fc1b,
                                                   const float* __restrict__ fc2w,
                                                   const float* __restrict__ fc2b,
                                                   float* __restrict__ out) {
    __shared__ float last[128], z[128];
    int b = blockIdx.x, tid = threadIdx.x;
    last[tid] = g_h0[((size_t)(TT - 1) * BB + b) * HH + tid];
    __syncthreads();
    float a = fc1b[tid];
#pragma unroll 4
    for (int k = 0; k < HH; k++) a = fmaf(last[k], fc1w[tid * HH + k], a);
    z[tid] = fmaxf(a, 0.f);
    __syncthreads();
    if (tid < 7) {
        float y = fc2b[tid];
#pragma unroll 4
        for (int k = 0; k < HH; k++) y = fmaf(z[k], fc2w[tid * HH + k], y);
        out[b * 7 + tid] = y;
    }
}

// ---------------- launcher ---------------------------------------------------
extern "C" void kernel_launch(void* const* d_in, const int* in_sizes, int n_in,
                              void* d_out, int out_size) {
    (void)in_sizes; (void)n_in; (void)out_size;
    const float* x    = (const float*)d_in[0];
    const float* wih0 = (const float*)d_in[1];
    const float* whh0 = (const float*)d_in[2];
    const float* bih0 = (const float*)d_in[3];
    const float* bhh0 = (const float*)d_in[4];
    const float* wih1 = (const float*)d_in[5];
    const float* whh1 = (const float*)d_in[6];
    const float* bih1 = (const float*)d_in[7];
    const float* bhh1 = (const float*)d_in[8];
    const float* wih2 = (const float*)d_in[9];
    const float* whh2 = (const float*)d_in[10];
    const float* bih2 = (const float*)d_in[11];
    const float* bhh2 = (const float*)d_in[12];
    const float* fc1w = (const float*)d_in[13];
    const float* fc1b = (const float*)d_in[14];
    const float* fc2w = (const float*)d_in[15];
    const float* fc2b = (const float*)d_in[16];
    float* out = (float*)d_out;

    cudaFuncSetAttribute(rec2_kernel, cudaFuncAttributeMaxDynamicSharedMemorySize, RSM_TOT);
    cudaFuncSetAttribute(proj_mma_kernel, cudaFuncAttributeMaxDynamicSharedMemorySize, SMW_TOT);

    prep_wfrag_kernel<<<384, 256>>>(whh0, whh1, whh2);                // 1
    prep_bias_kernel<<<6, 256>>>(bih0, bhh0, bih1, bhh1, bih2, bhh2); // 2
    proj0_kernel<<<512, 256>>>(x, wih0);                              // 3
    rec2_kernel<<<128, 512, RSM_TOT>>>(0, 0);                         // 4 -> g_h0 (ncu target)
    prep_b_kernel<<<256, 256>>>(wih1, wih2);                          // 5
    proj_mma_kernel<<<dim3(2048, 4), 256, SMW_TOT>>>(0);              // 6
    rec2_kernel<<<128, 512, RSM_TOT>>>(1, 1);                         // 7 -> g_h1
    proj_mma_kernel<<<dim3(2048, 4), 256, SMW_TOT>>>(1);              // 8
    rec2_kernel<<<128, 512, RSM_TOT>>>(2, 0);                         // 9 -> g_h0
    head_kernel<<<512, 128>>>(fc1w, fc1b, fc2w, fc2b, out);           // 10
}